// round 10
// baseline (speedup 1.0000x reference)
#include <cuda_runtime.h>
#include <cstdint>

#define BB 4
#define NN 8192
#define SS 2048
#define C1V 128
#define C2V 256
#define CCV 384
#define JJ (BB*NN)        // 32768
#define JZ (BB*SS)        // 8192
#define NRB (JJ/128)      // 256
#define KSPLIT 4
#define SCHUNK (SS/KSPLIT)  // 512

// ---------------- device scratch ----------------
__device__ float g_p2t[(size_t)JZ*C2V];            // points2 transposed (B*S, C2)
__device__ float g_z[(size_t)JZ*256];              // Z = p2t @ W0b^T
__device__ float g_kd[KSPLIT*JJ*3];                // knn candidates per S-chunk
__device__ int   g_ki[KSPLIT*JJ*3];
__device__ float g_y0[(size_t)JJ*256];
__device__ float g_y1[(size_t)JJ*128];
__device__ float g_p0s[NRB*256], g_p0q[NRB*256];
__device__ float g_p1s[NRB*128], g_p1q[NRB*128];
__device__ float g_sc0[256], g_sh0[256];
__device__ float g_sc1[128], g_sh1[128];

// ---------------- helpers ----------------
__device__ __forceinline__ uint32_t f2tf32(float x) {
    uint32_t r;
    asm("cvt.rna.tf32.f32 %0, %1;" : "=r"(r) : "f"(x));
    return r;
}
__device__ __forceinline__ float rtf(float x) { return __uint_as_float(f2tf32(x)); }
__device__ __forceinline__ void mma16n8k8(float* c, const uint32_t* a, const uint32_t* b) {
    asm volatile(
        "mma.sync.aligned.m16n8k8.row.col.f32.tf32.tf32.f32 "
        "{%0,%1,%2,%3}, {%4,%5,%6,%7}, {%8,%9}, {%0,%1,%2,%3};"
        : "+f"(c[0]), "+f"(c[1]), "+f"(c[2]), "+f"(c[3])
        : "r"(a[0]), "r"(a[1]), "r"(a[2]), "r"(a[3]), "r"(b[0]), "r"(b[1]));
}

// ---------------- K1: 3-NN over one S-chunk (512 candidates) ----------------
__global__ void knn_part(const float* __restrict__ xyz1, const float* __restrict__ xyz2) {
    __shared__ float4 pts[SCHUNK];
    const int b = blockIdx.y, half = blockIdx.z, soff = half * SCHUNK;
    const float* x2 = xyz2 + (size_t)b * 3 * SS + soff;
    for (int s = threadIdx.x; s < SCHUNK; s += blockDim.x) {
        float x = x2[s], y = x2[SS + s], z = x2[2 * SS + s];
        pts[s] = make_float4(x, y, z, x * x + y * y + z * z);
    }
    __syncthreads();
    const int n = blockIdx.x * blockDim.x + threadIdx.x;
    const float* x1 = xyz1 + (size_t)b * 3 * NN;
    const float qx = x1[n], qy = x1[NN + n], qz = x1[2 * NN + n];
    const float qn = qx * qx + qy * qy + qz * qz;
    float d0 = 3.4e38f, d1 = 3.4e38f, d2 = 3.4e38f;
    int   i0 = 0, i1 = 0, i2 = 0;
#pragma unroll 4
    for (int s = 0; s < SCHUNK; ++s) {
        float4 p = pts[s];
        float dot = fmaf(qx, p.x, fmaf(qy, p.y, qz * p.z));
        float d = fmaf(-2.f, dot, qn + p.w);
        if (d < d2) {
            if (d < d1) {
                d2 = d1; i2 = i1;
                if (d < d0) { d1 = d0; i1 = i0; d0 = d; i0 = s; }
                else        { d1 = d;  i1 = s; }
            } else { d2 = d; i2 = s; }
        }
    }
    const int j = b * NN + n;
    const size_t o = ((size_t)half * JJ + j) * 3;
    g_kd[o + 0] = d0; g_kd[o + 1] = d1; g_kd[o + 2] = d2;
    g_ki[o + 0] = soff + i0; g_ki[o + 1] = soff + i1; g_ki[o + 2] = soff + i2;
}

// ---------------- K2: points2 (B,C2,S) -> (B*S, C2) ----------------
__global__ void transpose_p2(const float* __restrict__ src) {
    __shared__ float tile[32][33];
    const int b = blockIdx.z;
    const int l0 = blockIdx.x * 32, c0 = blockIdx.y * 32;
    for (int i = threadIdx.y; i < 32; i += 8)
        tile[i][threadIdx.x] = src[((size_t)b * C2V + c0 + i) * SS + l0 + threadIdx.x];
    __syncthreads();
    for (int i = threadIdx.y; i < 32; i += 8)
        g_p2t[((size_t)b * SS + l0 + i) * C2V + c0 + threadIdx.x] = tile[threadIdx.x][i];
}

// ======== point-major mma GEMM: out = act(A) @ W^T (+bias) ========
// CTA tile (64*MT) x 64, 8 warps. MT=2: warp 32x32; MT=1: warp 16x32.
#define STRD 20
template<int KDIM, int NCOLS, int MT, bool ACT, bool RNDA, bool BNRED, bool HASBIAS>
__global__ __launch_bounds__(256) void gemm_pm(
    const float* __restrict__ A, const float* __restrict__ W, int wstride,
    const float* __restrict__ bias, float* __restrict__ out,
    const float* __restrict__ scale, const float* __restrict__ shift,
    float* __restrict__ psum, float* __restrict__ psq)
{
    constexpr int MROWS = 64 * MT;
    __shared__ float As[MROWS * STRD];
    __shared__ float Bs[64 * STRD];
    __shared__ float2 red_s[8 * 16], red_q[8 * 16];
    __shared__ float ssc[256], ssh[256];

    const int t = threadIdx.x, wid = t >> 5, lane = t & 31;
    const int j0 = blockIdx.x * MROWS, o0 = blockIdx.y * 64;
    const int wm = (wid >> 1) * 16 * MT, wn = (wid & 1) * 32;
    const int lr = lane >> 2, lk = lane & 3;

    if (ACT) {                     // only used with KDIM==256
        ssc[t] = scale[t];
        ssh[t] = shift[t];
        __syncthreads();
    }

    float acc[MT][4][4];
#pragma unroll
    for (int mt = 0; mt < MT; ++mt)
#pragma unroll
        for (int nt = 0; nt < 4; ++nt)
#pragma unroll
            for (int i = 0; i < 4; ++i) acc[mt][nt][i] = 0.f;

    const int arow = t >> 2, akq = (t & 3) * 4;
    const int brow = t >> 2, bkq = (t & 3) * 4;

    float4 pa0, pa1, pb;
    {
        const float* a0 = A + (size_t)(j0 + arow) * KDIM + akq;
        pa0 = *(const float4*)a0;
        if (MT == 2) pa1 = *(const float4*)(a0 + (size_t)64 * KDIM);
        pb  = *(const float4*)(W + (size_t)(o0 + brow) * wstride + bkq);
    }

    constexpr int NCHUNK = KDIM / 16;
    for (int c = 0; c < NCHUNK; ++c) {
        float4 va0 = pa0, va1 = pa1, vb = pb;
        if (ACT) {
            const int kb = c * 16 + akq;
            float s0 = ssc[kb], s1 = ssc[kb+1], s2 = ssc[kb+2], s3 = ssc[kb+3];
            float h0 = ssh[kb], h1 = ssh[kb+1], h2 = ssh[kb+2], h3 = ssh[kb+3];
            va0.x = rtf(fmaxf(fmaf(va0.x, s0, h0), 0.f));
            va0.y = rtf(fmaxf(fmaf(va0.y, s1, h1), 0.f));
            va0.z = rtf(fmaxf(fmaf(va0.z, s2, h2), 0.f));
            va0.w = rtf(fmaxf(fmaf(va0.w, s3, h3), 0.f));
            if (MT == 2) {
                va1.x = rtf(fmaxf(fmaf(va1.x, s0, h0), 0.f));
                va1.y = rtf(fmaxf(fmaf(va1.y, s1, h1), 0.f));
                va1.z = rtf(fmaxf(fmaf(va1.z, s2, h2), 0.f));
                va1.w = rtf(fmaxf(fmaf(va1.w, s3, h3), 0.f));
            }
        } else if (RNDA) {
            va0.x = rtf(va0.x); va0.y = rtf(va0.y); va0.z = rtf(va0.z); va0.w = rtf(va0.w);
            if (MT == 2) {
                va1.x = rtf(va1.x); va1.y = rtf(va1.y); va1.z = rtf(va1.z); va1.w = rtf(va1.w);
            }
        }
        vb.x = rtf(vb.x); vb.y = rtf(vb.y); vb.z = rtf(vb.z); vb.w = rtf(vb.w);
        *(float4*)&As[arow * STRD + akq] = va0;
        if (MT == 2) *(float4*)&As[(arow + 64) * STRD + akq] = va1;
        *(float4*)&Bs[brow * STRD + bkq] = vb;
        __syncthreads();

        if (c + 1 < NCHUNK) {
            const int k0 = (c + 1) * 16;
            const float* a0 = A + (size_t)(j0 + arow) * KDIM + k0 + akq;
            pa0 = *(const float4*)a0;
            if (MT == 2) pa1 = *(const float4*)(a0 + (size_t)64 * KDIM);
            pb  = *(const float4*)(W + (size_t)(o0 + brow) * wstride + k0 + bkq);
        }

#pragma unroll
        for (int kk = 0; kk < 2; ++kk) {
            uint32_t af[MT][4], bf[4][2];
            const int k = kk * 8 + lk;
#pragma unroll
            for (int mt = 0; mt < MT; ++mt) {
                const int r = wm + mt * 16 + lr;
                af[mt][0] = __float_as_uint(As[r * STRD + k]);
                af[mt][1] = __float_as_uint(As[(r + 8) * STRD + k]);
                af[mt][2] = __float_as_uint(As[r * STRD + k + 4]);
                af[mt][3] = __float_as_uint(As[(r + 8) * STRD + k + 4]);
            }
#pragma unroll
            for (int nt = 0; nt < 4; ++nt) {
                const int n = wn + nt * 8 + lr;
                bf[nt][0] = __float_as_uint(Bs[n * STRD + k]);
                bf[nt][1] = __float_as_uint(Bs[n * STRD + k + 4]);
            }
#pragma unroll
            for (int mt = 0; mt < MT; ++mt)
#pragma unroll
                for (int nt = 0; nt < 4; ++nt)
                    mma16n8k8(acc[mt][nt], af[mt], bf[nt]);
        }
        __syncthreads();
    }

    float2 sp[4], qp[4];
#pragma unroll
    for (int nt = 0; nt < 4; ++nt) { sp[nt] = make_float2(0.f, 0.f); qp[nt] = make_float2(0.f, 0.f); }
#pragma unroll
    for (int mt = 0; mt < MT; ++mt) {
        const int r0 = j0 + wm + mt * 16 + lr;
#pragma unroll
        for (int nt = 0; nt < 4; ++nt) {
            const int col = o0 + wn + nt * 8 + 2 * lk;
            float b0 = 0.f, b1 = 0.f;
            if (HASBIAS) { b0 = bias[col]; b1 = bias[col + 1]; }
            float v00 = acc[mt][nt][0] + b0, v01 = acc[mt][nt][1] + b1;
            float v10 = acc[mt][nt][2] + b0, v11 = acc[mt][nt][3] + b1;
            *(float2*)(out + (size_t)r0 * NCOLS + col)       = make_float2(v00, v01);
            *(float2*)(out + (size_t)(r0 + 8) * NCOLS + col) = make_float2(v10, v11);
            if (BNRED) {
                sp[nt].x += v00 + v10; sp[nt].y += v01 + v11;
                qp[nt].x += v00 * v00 + v10 * v10; qp[nt].y += v01 * v01 + v11 * v11;
            }
        }
    }
    if (BNRED) {
#pragma unroll
        for (int nt = 0; nt < 4; ++nt) {
#pragma unroll
            for (int off = 16; off >= 4; off >>= 1) {
                sp[nt].x += __shfl_xor_sync(0xffffffffu, sp[nt].x, off);
                sp[nt].y += __shfl_xor_sync(0xffffffffu, sp[nt].y, off);
                qp[nt].x += __shfl_xor_sync(0xffffffffu, qp[nt].x, off);
                qp[nt].y += __shfl_xor_sync(0xffffffffu, qp[nt].y, off);
            }
        }
        if (lane < 4) {
#pragma unroll
            for (int nt = 0; nt < 4; ++nt) {
                red_s[wid * 16 + nt * 4 + lane] = sp[nt];
                red_q[wid * 16 + nt * 4 + lane] = qp[nt];
            }
        }
        __syncthreads();
        if (t < 64) {
            const int wnq = t >> 5, nt = (t >> 3) & 3, lkq = (t >> 1) & 3, hf = t & 1;
            float s = 0.f, q = 0.f;
#pragma unroll
            for (int wq = 0; wq < 4; ++wq) {
                const int w = wq * 2 + wnq;
                float2 a = red_s[w * 16 + nt * 4 + lkq];
                float2 c2 = red_q[w * 16 + nt * 4 + lkq];
                s += hf ? a.y : a.x;
                q += hf ? c2.y : c2.x;
            }
            psum[(size_t)blockIdx.x * NCOLS + o0 + t] = s;
            psq [(size_t)blockIdx.x * NCOLS + o0 + t] = q;
        }
    }
}

// ======== GEMM0: y0 = T(points1) @ W0a^T + b0 + gathered Z, + BN partials ========
// K=128, fused transpose A-loader; knn candidate merge folded into staging.
// Dynamic smem layout (bytes):
//   As    [0, 8704)        16 k x 136 floats
//   Bs    [8704, 13824)    64 x 20
//   sidx  [13824, 15360)   128 x 3 int
//   swgt  [15360, 16896)   128 x 3 float
//   red   [16896, 20992)   2 x 8x16 float2
//   Zs    [20992, 55808)   128 x 68 floats
#define G0_SMEM 55808
__global__ __launch_bounds__(256) void gemm0_kernel(
    const float* __restrict__ P1, const float* __restrict__ W,
    const float* __restrict__ bias, float* __restrict__ out,
    float* __restrict__ psum, float* __restrict__ psq)
{
    extern __shared__ char dyn[];
    float*  As    = (float*)(dyn);
    float*  Bs    = (float*)(dyn + 8704);
    int*    sidx  = (int*)  (dyn + 13824);
    float*  swgt  = (float*)(dyn + 15360);
    float2* red_s = (float2*)(dyn + 16896);
    float2* red_q = red_s + 8 * 16;
    float*  Zs    = (float*)(dyn + 20992);

    const int t = threadIdx.x, wid = t >> 5, lane = t & 31;
    const int j0 = blockIdx.x * 128, o0 = blockIdx.y * 64;
    const int b = j0 >> 13, n0 = j0 & (NN - 1);
    const int wm = (wid >> 1) * 32, wn = (wid & 1) * 32;
    const int lr = lane >> 2, lk = lane & 3;

    // merge KSPLIT sorted 3-candidate lists -> final 3-NN + weights
    if (t < 128) {
        const int j = j0 + t;
        float md0 = 3.4e38f, md1 = 3.4e38f, md2 = 3.4e38f;
        int   mi0 = 0, mi1 = 0, mi2 = 0;
#pragma unroll
        for (int h = 0; h < KSPLIT; ++h) {
            const size_t o = ((size_t)h * JJ + j) * 3;
#pragma unroll
            for (int m = 0; m < 3; ++m) {
                float d = g_kd[o + m];
                int   i = g_ki[o + m];
                if (d < md2) {
                    if (d < md1) {
                        md2 = md1; mi2 = mi1;
                        if (d < md0) { md1 = md0; mi1 = mi0; md0 = d; mi0 = i; }
                        else         { md1 = d;  mi1 = i; }
                    } else { md2 = d; mi2 = i; }
                }
            }
        }
        float r0 = 1.f / (md0 + 1e-8f), r1 = 1.f / (md1 + 1e-8f), r2 = 1.f / (md2 + 1e-8f);
        float inv = 1.f / (r0 + r1 + r2);
        sidx[t * 3 + 0] = mi0; sidx[t * 3 + 1] = mi1; sidx[t * 3 + 2] = mi2;
        swgt[t * 3 + 0] = r0 * inv; swgt[t * 3 + 1] = r1 * inv; swgt[t * 3 + 2] = r2 * inv;
    }
    __syncthreads();

    const int cA = t >> 4, gA = t & 15;
    const int brow = t >> 2, bkq = (t & 3) * 4;

    float acc[2][4][4];
#pragma unroll
    for (int mt = 0; mt < 2; ++mt)
#pragma unroll
        for (int nt = 0; nt < 4; ++nt)
#pragma unroll
            for (int i = 0; i < 4; ++i) acc[mt][nt][i] = 0.f;

    float4 ra0, ra1, pb;
    {
        const float* bp = P1 + ((size_t)b * C1V + cA) * NN + n0 + gA * 4;
        ra0 = *(const float4*)bp;
        ra1 = *(const float4*)(bp + 64);
        pb  = *(const float4*)&W[(size_t)(o0 + brow) * CCV + bkq];
    }

    constexpr int NCHUNK = 8;   // K = 128
    for (int c = 0; c < NCHUNK; ++c) {
        uint4 u0, u1;
        u0.x = f2tf32(ra0.x); u0.y = f2tf32(ra0.y); u0.z = f2tf32(ra0.z); u0.w = f2tf32(ra0.w);
        u1.x = f2tf32(ra1.x); u1.y = f2tf32(ra1.y); u1.z = f2tf32(ra1.z); u1.w = f2tf32(ra1.w);
        *(uint4*)&As[cA * 136 + gA * 4]      = u0;
        *(uint4*)&As[cA * 136 + 64 + gA * 4] = u1;
        float4 vb = pb;
        vb.x = rtf(vb.x); vb.y = rtf(vb.y); vb.z = rtf(vb.z); vb.w = rtf(vb.w);
        *(float4*)&Bs[brow * 20 + bkq] = vb;
        __syncthreads();

        if (c + 1 < NCHUNK) {
            const int k0 = (c + 1) * 16;
            const float* bp = P1 + ((size_t)b * C1V + k0 + cA) * NN + n0 + gA * 4;
            ra0 = *(const float4*)bp;
            ra1 = *(const float4*)(bp + 64);
            pb  = *(const float4*)&W[(size_t)(o0 + brow) * CCV + k0 + bkq];
        }

#pragma unroll
        for (int kk = 0; kk < 2; ++kk) {
            uint32_t af[2][4], bf[4][2];
            const int k = kk * 8 + lk;
#pragma unroll
            for (int mt = 0; mt < 2; ++mt) {
                const int r = wm + mt * 16 + lr;
                af[mt][0] = __float_as_uint(As[k * 136 + r]);
                af[mt][1] = __float_as_uint(As[k * 136 + r + 8]);
                af[mt][2] = __float_as_uint(As[(k + 4) * 136 + r]);
                af[mt][3] = __float_as_uint(As[(k + 4) * 136 + r + 8]);
            }
#pragma unroll
            for (int nt = 0; nt < 4; ++nt) {
                const int n = wn + nt * 8 + lr;
                bf[nt][0] = __float_as_uint(Bs[n * 20 + k]);
                bf[nt][1] = __float_as_uint(Bs[n * 20 + k + 4]);
            }
#pragma unroll
            for (int mt = 0; mt < 2; ++mt)
#pragma unroll
                for (int nt = 0; nt < 4; ++nt)
                    mma16n8k8(acc[mt][nt], af[mt], bf[nt]);
        }
        __syncthreads();
    }

    // gather weighted Z rows into Zs (4 threads per row cover 64 cols)
    {
        const int rg = t >> 2, qg = t & 3;
#pragma unroll
        for (int rr = 0; rr < 2; ++rr) {
            const int row = rg + rr * 64;
            const int s0 = sidx[row * 3 + 0], s1 = sidx[row * 3 + 1], s2 = sidx[row * 3 + 2];
            const float w0v = swgt[row * 3 + 0], w1v = swgt[row * 3 + 1], w2v = swgt[row * 3 + 2];
            const float* z0 = g_z + ((size_t)b * SS + s0) * 256 + o0 + qg * 16;
            const float* z1 = g_z + ((size_t)b * SS + s1) * 256 + o0 + qg * 16;
            const float* z2 = g_z + ((size_t)b * SS + s2) * 256 + o0 + qg * 16;
#pragma unroll
            for (int i = 0; i < 4; ++i) {
                float4 a = *(const float4*)(z0 + i * 4);
                float4 bq = *(const float4*)(z1 + i * 4);
                float4 cq = *(const float4*)(z2 + i * 4);
                float4 v;
                v.x = w0v * a.x + w1v * bq.x + w2v * cq.x;
                v.y = w0v * a.y + w1v * bq.y + w2v * cq.y;
                v.z = w0v * a.z + w1v * bq.z + w2v * cq.z;
                v.w = w0v * a.w + w1v * bq.w + w2v * cq.w;
                *(float4*)&Zs[row * 68 + qg * 16 + i * 4] = v;
            }
        }
    }
    __syncthreads();

    // epilogue: bias + Zs + store + BN partials
    float2 sp[4], qp[4];
#pragma unroll
    for (int nt = 0; nt < 4; ++nt) { sp[nt] = make_float2(0.f, 0.f); qp[nt] = make_float2(0.f, 0.f); }
#pragma unroll
    for (int mt = 0; mt < 2; ++mt) {
        const int rloc = wm + mt * 16 + lr;
        const int r0 = j0 + rloc;
#pragma unroll
        for (int nt = 0; nt < 4; ++nt) {
            const int cloc = wn + nt * 8 + 2 * lk;
            const int col = o0 + cloc;
            const float b0 = bias[col], b1 = bias[col + 1];
            float v00 = acc[mt][nt][0] + b0 + Zs[rloc * 68 + cloc];
            float v01 = acc[mt][nt][1] + b1 + Zs[rloc * 68 + cloc + 1];
            float v10 = acc[mt][nt][2] + b0 + Zs[(rloc + 8) * 68 + cloc];
            float v11 = acc[mt][nt][3] + b1 + Zs[(rloc + 8) * 68 + cloc + 1];
            *(float2*)(out + (size_t)r0 * 256 + col)       = make_float2(v00, v01);
            *(float2*)(out + (size_t)(r0 + 8) * 256 + col) = make_float2(v10, v11);
            sp[nt].x += v00 + v10; sp[nt].y += v01 + v11;
            qp[nt].x += v00 * v00 + v10 * v10; qp[nt].y += v01 * v01 + v11 * v11;
        }
    }
#pragma unroll
    for (int nt = 0; nt < 4; ++nt) {
#pragma unroll
        for (int off = 16; off >= 4; off >>= 1) {
            sp[nt].x += __shfl_xor_sync(0xffffffffu, sp[nt].x, off);
            sp[nt].y += __shfl_xor_sync(0xffffffffu, sp[nt].y, off);
            qp[nt].x += __shfl_xor_sync(0xffffffffu, qp[nt].x, off);
            qp[nt].y += __shfl_xor_sync(0xffffffffu, qp[nt].y, off);
        }
    }
    if (lane < 4) {
#pragma unroll
        for (int nt = 0; nt < 4; ++nt) {
            red_s[wid * 16 + nt * 4 + lane] = sp[nt];
            red_q[wid * 16 + nt * 4 + lane] = qp[nt];
        }
    }
    __syncthreads();
    if (t < 64) {
        const int wnq = t >> 5, nt = (t >> 3) & 3, lkq = (t >> 1) & 3, hf = t & 1;
        float s = 0.f, q = 0.f;
#pragma unroll
        for (int wq = 0; wq < 4; ++wq) {
            const int w = wq * 2 + wnq;
            float2 a = red_s[w * 16 + nt * 4 + lkq];
            float2 c2 = red_q[w * 16 + nt * 4 + lkq];
            s += hf ? a.y : a.x;
            q += hf ? c2.y : c2.x;
        }
        psum[(size_t)blockIdx.x * 256 + o0 + t] = s;
        psq [(size_t)blockIdx.x * 256 + o0 + t] = q;
    }
}

// ---------------- finalize BN scale/shift ----------------
__global__ void finalize_bn(const float* __restrict__ psum, const float* __restrict__ psq,
                            int C, const float* __restrict__ gamma, const float* __restrict__ beta,
                            float* __restrict__ scale, float* __restrict__ shift) {
    const int o = threadIdx.x;
    if (o >= C) return;
    float s = 0.f, q = 0.f;
    for (int r = 0; r < NRB; ++r) { s += psum[(size_t)r * C + o]; q += psq[(size_t)r * C + o]; }
    const float invn = 1.f / (float)JJ;
    float m = s * invn;
    float var = q * invn - m * m;
    float sc = gamma[o] * rsqrtf(var + 1e-5f);
    scale[o] = sc;
    shift[o] = beta[o] - m * sc;
}

// ---------------- output: BN1+ReLU + transpose to (B,128,N) ----------------
__global__ void output_kernel(float* __restrict__ out) {
    __shared__ float tile[32][33];
    const int b = blockIdx.z;
    const int n0 = blockIdx.x * 32, p0 = blockIdx.y * 32;
    const int tx = threadIdx.x;
    for (int i = threadIdx.y; i < 32; i += 8) {
        int p = p0 + tx, n = n0 + i;
        float v = g_y1[((size_t)b * NN + n) * 128 + p];
        tile[i][tx] = fmaxf(fmaf(v, g_sc1[p], g_sh1[p]), 0.f);
    }
    __syncthreads();
    for (int i = threadIdx.y; i < 32; i += 8)
        out[((size_t)(b * 128) + p0 + i) * NN + n0 + tx] = tile[tx][i];
}

// ---------------- launch ----------------
extern "C" void kernel_launch(void* const* d_in, const int* in_sizes, int n_in,
                              void* d_out, int out_size) {
    const float* xyz1    = (const float*)d_in[0];
    const float* xyz2    = (const float*)d_in[1];
    const float* points1 = (const float*)d_in[2];
    const float* points2 = (const float*)d_in[3];
    const float* w0      = (const float*)d_in[4];
    const float* b0      = (const float*)d_in[5];
    const float* gamma0  = (const float*)d_in[6];
    const float* beta0   = (const float*)d_in[7];
    const float* w1      = (const float*)d_in[8];
    const float* b1      = (const float*)d_in[9];
    const float* gamma1  = (const float*)d_in[10];
    const float* beta1   = (const float*)d_in[11];
    float* out = (float*)d_out;

    float *p2t, *zbuf, *y0, *y1, *p0s, *p0q, *p1s, *p1q, *sc0, *sh0, *sc1, *sh1;
    cudaGetSymbolAddress((void**)&p2t,  g_p2t);
    cudaGetSymbolAddress((void**)&zbuf, g_z);
    cudaGetSymbolAddress((void**)&y0,   g_y0);
    cudaGetSymbolAddress((void**)&y1,   g_y1);
    cudaGetSymbolAddress((void**)&p0s,  g_p0s);
    cudaGetSymbolAddress((void**)&p0q,  g_p0q);
    cudaGetSymbolAddress((void**)&p1s,  g_p1s);
    cudaGetSymbolAddress((void**)&p1q,  g_p1q);
    cudaGetSymbolAddress((void**)&sc0,  g_sc0);
    cudaGetSymbolAddress((void**)&sh0,  g_sh0);
    cudaGetSymbolAddress((void**)&sc1,  g_sc1);
    cudaGetSymbolAddress((void**)&sh1,  g_sh1);

    cudaFuncSetAttribute(gemm0_kernel, cudaFuncAttributeMaxDynamicSharedMemorySize, G0_SMEM);

    // 1: knn candidates (4-way S split)
    knn_part<<<dim3(NN / 256, BB, KSPLIT), 256>>>(xyz1, xyz2);
    // 2: transpose points2
    transpose_p2<<<dim3(SS / 32, C2V / 32, BB), dim3(32, 8)>>>(points2);
    // 3: Z = p2t @ W0b^T   (64-row tiles -> 512 CTAs)
    gemm_pm<256, 256, 1, false, true, false, false><<<dim3(JZ / 64, 4), 256>>>(
        p2t, w0 + 128, CCV, nullptr, zbuf, nullptr, nullptr, nullptr, nullptr);
    // 4 (profiled): y0 = T(points1) @ W0a^T + b0 + gather(Z), + BN partials (+knn merge)
    gemm0_kernel<<<dim3(NRB, 4), 256, G0_SMEM>>>(points1, w0, b0, y0, p0s, p0q);
    // 5: BN0 finalize
    finalize_bn<<<1, 256>>>(p0s, p0q, 256, gamma0, beta0, sc0, sh0);
    // 6: y1 = relu(bn0(y0)) @ W1^T + b1, + BN partials
    gemm_pm<256, 128, 2, true, false, true, true><<<dim3(NRB, 2), 256>>>(
        y0, w1, 256, b1, y1, sc0, sh0, p1s, p1q);
    // 7: BN1 finalize
    finalize_bn<<<1, 128>>>(p1s, p1q, 128, gamma1, beta1, sc1, sh1);
    // 8: output transpose + BN1 + ReLU
    output_kernel<<<dim3(NN / 32, 128 / 32, BB), dim3(32, 8)>>>(out);
}

// round 11
// speedup vs baseline: 1.0721x; 1.0721x over previous
#include <cuda_runtime.h>
#include <cstdint>

#define BB 4
#define NN 8192
#define SS 2048
#define C1V 128
#define C2V 256
#define CCV 384
#define JJ (BB*NN)        // 32768
#define JZ (BB*SS)        // 8192
#define NRB (JJ/128)      // 256
#define KSPLIT 4
#define SCHUNK (SS/KSPLIT)  // 512

// ---------------- device scratch ----------------
__device__ float g_p2t[(size_t)JZ*C2V];            // points2 transposed (B*S, C2), tf32-rounded
__device__ float g_z[(size_t)JZ*256];              // Z = p2t @ W0b^T
__device__ float g_kd[KSPLIT*JJ*3];
__device__ int   g_ki[KSPLIT*JJ*3];
__device__ int   g_idx[JJ*3];
__device__ float g_wgt[JJ*3];
__device__ float g_y0[(size_t)JJ*256];
__device__ float g_y1[(size_t)JJ*128];
__device__ float g_p0s[NRB*256], g_p0q[NRB*256];
__device__ float g_p1s[NRB*128], g_p1q[NRB*128];
__device__ float g_sc0[256], g_sh0[256];
__device__ float g_sc1[128], g_sh1[128];

// ---------------- helpers ----------------
__device__ __forceinline__ uint32_t f2tf32(float x) {
    uint32_t r;
    asm("cvt.rna.tf32.f32 %0, %1;" : "=r"(r) : "f"(x));
    return r;
}
__device__ __forceinline__ float rtf(float x) { return __uint_as_float(f2tf32(x)); }
__device__ __forceinline__ void mma16n8k8(float* c, const uint32_t* a, const uint32_t* b) {
    asm volatile(
        "mma.sync.aligned.m16n8k8.row.col.f32.tf32.tf32.f32 "
        "{%0,%1,%2,%3}, {%4,%5,%6,%7}, {%8,%9}, {%0,%1,%2,%3};"
        : "+f"(c[0]), "+f"(c[1]), "+f"(c[2]), "+f"(c[3])
        : "r"(a[0]), "r"(a[1]), "r"(a[2]), "r"(a[3]), "r"(b[0]), "r"(b[1]));
}

// ---------------- K1: 3-NN over one S-chunk ----------------
__global__ void knn_part(const float* __restrict__ xyz1, const float* __restrict__ xyz2) {
    __shared__ float4 pts[SCHUNK];
    const int b = blockIdx.y, half = blockIdx.z, soff = half * SCHUNK;
    const float* x2 = xyz2 + (size_t)b * 3 * SS + soff;
    for (int s = threadIdx.x; s < SCHUNK; s += blockDim.x) {
        float x = x2[s], y = x2[SS + s], z = x2[2 * SS + s];
        pts[s] = make_float4(x, y, z, x * x + y * y + z * z);
    }
    __syncthreads();
    const int n = blockIdx.x * blockDim.x + threadIdx.x;
    const float* x1 = xyz1 + (size_t)b * 3 * NN;
    const float qx = x1[n], qy = x1[NN + n], qz = x1[2 * NN + n];
    const float qn = qx * qx + qy * qy + qz * qz;
    float d0 = 3.4e38f, d1 = 3.4e38f, d2 = 3.4e38f;
    int   i0 = 0, i1 = 0, i2 = 0;
#pragma unroll 4
    for (int s = 0; s < SCHUNK; ++s) {
        float4 p = pts[s];
        float dot = fmaf(qx, p.x, fmaf(qy, p.y, qz * p.z));
        float d = fmaf(-2.f, dot, qn + p.w);
        if (d < d2) {
            if (d < d1) {
                d2 = d1; i2 = i1;
                if (d < d0) { d1 = d0; i1 = i0; d0 = d; i0 = s; }
                else        { d1 = d;  i1 = s; }
            } else { d2 = d; i2 = s; }
        }
    }
    const int j = b * NN + n;
    const size_t o = ((size_t)half * JJ + j) * 3;
    g_kd[o + 0] = d0; g_kd[o + 1] = d1; g_kd[o + 2] = d2;
    g_ki[o + 0] = soff + i0; g_ki[o + 1] = soff + i1; g_ki[o + 2] = soff + i2;
}

// ---------------- K1b: merge candidate lists + weights ----------------
__global__ void knn_merge() {
    const int j = blockIdx.x * 256 + threadIdx.x;
    float md0 = 3.4e38f, md1 = 3.4e38f, md2 = 3.4e38f;
    int   mi0 = 0, mi1 = 0, mi2 = 0;
#pragma unroll
    for (int h = 0; h < KSPLIT; ++h) {
        const size_t o = ((size_t)h * JJ + j) * 3;
#pragma unroll
        for (int m = 0; m < 3; ++m) {
            float d = g_kd[o + m];
            int   i = g_ki[o + m];
            if (d < md2) {
                if (d < md1) {
                    md2 = md1; mi2 = mi1;
                    if (d < md0) { md1 = md0; mi1 = mi0; md0 = d; mi0 = i; }
                    else         { md1 = d;  mi1 = i; }
                } else { md2 = d; mi2 = i; }
            }
        }
    }
    float r0 = 1.f / (md0 + 1e-8f), r1 = 1.f / (md1 + 1e-8f), r2 = 1.f / (md2 + 1e-8f);
    float inv = 1.f / (r0 + r1 + r2);
    g_idx[j * 3 + 0] = mi0; g_idx[j * 3 + 1] = mi1; g_idx[j * 3 + 2] = mi2;
    g_wgt[j * 3 + 0] = r0 * inv; g_wgt[j * 3 + 1] = r1 * inv; g_wgt[j * 3 + 2] = r2 * inv;
}

// ---------------- K2: points2 (B,C2,S) -> (B*S, C2), tf32-rounded ----------------
__global__ void transpose_p2(const float* __restrict__ src) {
    __shared__ float tile[32][33];
    const int b = blockIdx.z;
    const int l0 = blockIdx.x * 32, c0 = blockIdx.y * 32;
    for (int i = threadIdx.y; i < 32; i += 8)
        tile[i][threadIdx.x] = src[((size_t)b * C2V + c0 + i) * SS + l0 + threadIdx.x];
    __syncthreads();
    for (int i = threadIdx.y; i < 32; i += 8)
        g_p2t[((size_t)b * SS + l0 + i) * C2V + c0 + threadIdx.x] = rtf(tile[threadIdx.x][i]);
}

// ======== point-major mma GEMM: out = act(A) @ W^T (+bias) ========
// CTA tile (64*MT) x 64, 8 warps (4m x 2n), double-buffered smem, 1 sync/chunk.
#define STRD 20
template<int KDIM, int NCOLS, int MT, bool ACT, bool BNRED, bool HASBIAS>
__global__ __launch_bounds__(256) void gemm_pm(
    const float* __restrict__ A, const float* __restrict__ W, int wstride,
    const float* __restrict__ bias, float* __restrict__ out,
    const float* __restrict__ scale, const float* __restrict__ shift,
    float* __restrict__ psum, float* __restrict__ psq)
{
    constexpr int MROWS = 64 * MT;
    __shared__ float As[2][MROWS * STRD];
    __shared__ float Bs[2][64 * STRD];
    __shared__ float2 red_s[8 * 16], red_q[8 * 16];
    __shared__ float ssc[256], ssh[256];

    const int t = threadIdx.x, wid = t >> 5, lane = t & 31;
    const int j0 = blockIdx.x * MROWS, o0 = blockIdx.y * 64;
    const int wm = (wid >> 1) * 16 * MT, wn = (wid & 1) * 32;
    const int lr = lane >> 2, lk = lane & 3;

    if (ACT) {
        ssc[t] = scale[t]; ssh[t] = shift[t];
        __syncthreads();
    }

    float acc[MT][4][4];
#pragma unroll
    for (int mt = 0; mt < MT; ++mt)
#pragma unroll
        for (int nt = 0; nt < 4; ++nt)
#pragma unroll
            for (int i = 0; i < 4; ++i) acc[mt][nt][i] = 0.f;

    const int arow = t >> 2, akq = (t & 3) * 4;

    float4 pa0, pa1, pb;
    {
        const float* a0 = A + (size_t)(j0 + arow) * KDIM + akq;
        pa0 = *(const float4*)a0;
        if (MT == 2) pa1 = *(const float4*)(a0 + (size_t)64 * KDIM);
        pb  = *(const float4*)(W + (size_t)(o0 + arow) * wstride + akq);
    }

    constexpr int NCHUNK = KDIM / 16;
    for (int c = 0; c < NCHUNK; ++c) {
        float* Ab = As[c & 1];
        float* Bb = Bs[c & 1];
        float4 va0 = pa0, va1 = pa1, vb = pb;
        if (ACT) {
            const int kb = c * 16 + akq;
            float s0 = ssc[kb], s1 = ssc[kb+1], s2 = ssc[kb+2], s3 = ssc[kb+3];
            float h0 = ssh[kb], h1 = ssh[kb+1], h2 = ssh[kb+2], h3 = ssh[kb+3];
            va0.x = rtf(fmaxf(fmaf(va0.x, s0, h0), 0.f));
            va0.y = rtf(fmaxf(fmaf(va0.y, s1, h1), 0.f));
            va0.z = rtf(fmaxf(fmaf(va0.z, s2, h2), 0.f));
            va0.w = rtf(fmaxf(fmaf(va0.w, s3, h3), 0.f));
            if (MT == 2) {
                va1.x = rtf(fmaxf(fmaf(va1.x, s0, h0), 0.f));
                va1.y = rtf(fmaxf(fmaf(va1.y, s1, h1), 0.f));
                va1.z = rtf(fmaxf(fmaf(va1.z, s2, h2), 0.f));
                va1.w = rtf(fmaxf(fmaf(va1.w, s3, h3), 0.f));
            }
        }
        vb.x = rtf(vb.x); vb.y = rtf(vb.y); vb.z = rtf(vb.z); vb.w = rtf(vb.w);
        *(float4*)&Ab[arow * STRD + akq] = va0;
        if (MT == 2) *(float4*)&Ab[(arow + 64) * STRD + akq] = va1;
        *(float4*)&Bb[arow * STRD + akq] = vb;

        if (c + 1 < NCHUNK) {
            const int k0 = (c + 1) * 16;
            const float* a0 = A + (size_t)(j0 + arow) * KDIM + k0 + akq;
            pa0 = *(const float4*)a0;
            if (MT == 2) pa1 = *(const float4*)(a0 + (size_t)64 * KDIM);
            pb  = *(const float4*)(W + (size_t)(o0 + arow) * wstride + k0 + akq);
        }
        __syncthreads();

#pragma unroll
        for (int kk = 0; kk < 2; ++kk) {
            uint32_t af[MT][4], bf[4][2];
            const int k = kk * 8 + lk;
#pragma unroll
            for (int mt = 0; mt < MT; ++mt) {
                const int r = wm + mt * 16 + lr;
                af[mt][0] = __float_as_uint(Ab[r * STRD + k]);
                af[mt][1] = __float_as_uint(Ab[(r + 8) * STRD + k]);
                af[mt][2] = __float_as_uint(Ab[r * STRD + k + 4]);
                af[mt][3] = __float_as_uint(Ab[(r + 8) * STRD + k + 4]);
            }
#pragma unroll
            for (int nt = 0; nt < 4; ++nt) {
                const int n = wn + nt * 8 + lr;
                bf[nt][0] = __float_as_uint(Bb[n * STRD + k]);
                bf[nt][1] = __float_as_uint(Bb[n * STRD + k + 4]);
            }
#pragma unroll
            for (int mt = 0; mt < MT; ++mt)
#pragma unroll
                for (int nt = 0; nt < 4; ++nt)
                    mma16n8k8(acc[mt][nt], af[mt], bf[nt]);
        }
        // no trailing sync: next chunk writes the other buffer; writes to THIS
        // buffer happen only after the next sync, which all warps reach only
        // after finishing this compute.
    }

    float2 sp[4], qp[4];
#pragma unroll
    for (int nt = 0; nt < 4; ++nt) { sp[nt] = make_float2(0.f, 0.f); qp[nt] = make_float2(0.f, 0.f); }
#pragma unroll
    for (int mt = 0; mt < MT; ++mt) {
        const int r0 = j0 + wm + mt * 16 + lr;
#pragma unroll
        for (int nt = 0; nt < 4; ++nt) {
            const int col = o0 + wn + nt * 8 + 2 * lk;
            float b0 = 0.f, b1 = 0.f;
            if (HASBIAS) { b0 = bias[col]; b1 = bias[col + 1]; }
            float v00 = acc[mt][nt][0] + b0, v01 = acc[mt][nt][1] + b1;
            float v10 = acc[mt][nt][2] + b0, v11 = acc[mt][nt][3] + b1;
            *(float2*)(out + (size_t)r0 * NCOLS + col)       = make_float2(v00, v01);
            *(float2*)(out + (size_t)(r0 + 8) * NCOLS + col) = make_float2(v10, v11);
            if (BNRED) {
                sp[nt].x += v00 + v10; sp[nt].y += v01 + v11;
                qp[nt].x += v00 * v00 + v10 * v10; qp[nt].y += v01 * v01 + v11 * v11;
            }
        }
    }
    if (BNRED) {
#pragma unroll
        for (int nt = 0; nt < 4; ++nt) {
#pragma unroll
            for (int off = 16; off >= 4; off >>= 1) {
                sp[nt].x += __shfl_xor_sync(0xffffffffu, sp[nt].x, off);
                sp[nt].y += __shfl_xor_sync(0xffffffffu, sp[nt].y, off);
                qp[nt].x += __shfl_xor_sync(0xffffffffu, qp[nt].x, off);
                qp[nt].y += __shfl_xor_sync(0xffffffffu, qp[nt].y, off);
            }
        }
        __syncthreads();   // mainloop buffers dead; reuse barrier before red arrays
        if (lane < 4) {
#pragma unroll
            for (int nt = 0; nt < 4; ++nt) {
                red_s[wid * 16 + nt * 4 + lane] = sp[nt];
                red_q[wid * 16 + nt * 4 + lane] = qp[nt];
            }
        }
        __syncthreads();
        if (t < 64) {
            const int wnq = t >> 5, nt = (t >> 3) & 3, lkq = (t >> 1) & 3, hf = t & 1;
            float s = 0.f, q = 0.f;
#pragma unroll
            for (int wq = 0; wq < 4; ++wq) {
                const int w = wq * 2 + wnq;
                float2 a = red_s[w * 16 + nt * 4 + lkq];
                float2 c2 = red_q[w * 16 + nt * 4 + lkq];
                s += hf ? a.y : a.x;
                q += hf ? c2.y : c2.x;
            }
            psum[(size_t)blockIdx.x * NCOLS + o0 + t] = s;
            psq [(size_t)blockIdx.x * NCOLS + o0 + t] = q;
        }
    }
}

// ======== GEMM0: 128x128 tile, K=128; y0 = T(points1)@W0a^T + b0 + gather(Z) ========
// A staged k-major (transpose loader), double-buffered, 1 sync/chunk.
// Epilogue: register gather of weighted Z rows (L2-resident), bias, BN partials.
__global__ __launch_bounds__(256) void gemm0_kernel(
    const float* __restrict__ P1, const float* __restrict__ W,
    const float* __restrict__ bias, float* __restrict__ out,
    float* __restrict__ psum, float* __restrict__ psq)
{
    __shared__ float As[2][16 * 136];     // [k][row], conflict-free fragments
    __shared__ float Bs[2][128 * STRD];
    __shared__ float2 red_s[8 * 32], red_q[8 * 32];
    __shared__ int   sidx[128 * 3];
    __shared__ float swgt[128 * 3];

    const int t = threadIdx.x, wid = t >> 5, lane = t & 31;
    const int j0 = blockIdx.x * 128, o0 = blockIdx.y * 128;
    const int b = j0 >> 13, n0 = j0 & (NN - 1);
    const int wm = (wid >> 1) * 32, wn = (wid & 1) * 64;
    const int lr = lane >> 2, lk = lane & 3;

    if (t < 128) {
#pragma unroll
        for (int m = 0; m < 3; ++m) sidx[t * 3 + m] = g_idx[(size_t)(j0 + t) * 3 + m];
    } else {
        int r = t - 128;
#pragma unroll
        for (int m = 0; m < 3; ++m) swgt[r * 3 + m] = g_wgt[(size_t)(j0 + r) * 3 + m];
    }

    const int cA = t >> 4, gA = t & 15;           // A: channel cA, rows gA*4.. & +64
    const int brow = t >> 2, bkq = (t & 3) * 4;   // B: rows brow & brow+64

    float acc[2][8][4];
#pragma unroll
    for (int mt = 0; mt < 2; ++mt)
#pragma unroll
        for (int nt = 0; nt < 8; ++nt)
#pragma unroll
            for (int i = 0; i < 4; ++i) acc[mt][nt][i] = 0.f;

    float4 ra0, ra1, rb0, rb1;
    {
        const float* ap = P1 + ((size_t)b * C1V + cA) * NN + n0 + gA * 4;
        ra0 = *(const float4*)ap;
        ra1 = *(const float4*)(ap + 64);
        rb0 = *(const float4*)&W[(size_t)(o0 + brow) * CCV + bkq];
        rb1 = *(const float4*)&W[(size_t)(o0 + brow + 64) * CCV + bkq];
    }
    __syncthreads();   // sidx/swgt ready (also separates from staging below)

    constexpr int NCHUNK = 8;   // K = 128
    for (int c = 0; c < NCHUNK; ++c) {
        float* Ab = As[c & 1];
        float* Bb = Bs[c & 1];
        uint4 u0, u1;
        u0.x = f2tf32(ra0.x); u0.y = f2tf32(ra0.y); u0.z = f2tf32(ra0.z); u0.w = f2tf32(ra0.w);
        u1.x = f2tf32(ra1.x); u1.y = f2tf32(ra1.y); u1.z = f2tf32(ra1.z); u1.w = f2tf32(ra1.w);
        *(uint4*)&Ab[cA * 136 + gA * 4]      = u0;
        *(uint4*)&Ab[cA * 136 + 64 + gA * 4] = u1;
        float4 v0 = rb0, v1 = rb1;
        v0.x = rtf(v0.x); v0.y = rtf(v0.y); v0.z = rtf(v0.z); v0.w = rtf(v0.w);
        v1.x = rtf(v1.x); v1.y = rtf(v1.y); v1.z = rtf(v1.z); v1.w = rtf(v1.w);
        *(float4*)&Bb[brow * STRD + bkq]        = v0;
        *(float4*)&Bb[(brow + 64) * STRD + bkq] = v1;

        if (c + 1 < NCHUNK) {
            const int k0 = (c + 1) * 16;
            const float* ap = P1 + ((size_t)b * C1V + k0 + cA) * NN + n0 + gA * 4;
            ra0 = *(const float4*)ap;
            ra1 = *(const float4*)(ap + 64);
            rb0 = *(const float4*)&W[(size_t)(o0 + brow) * CCV + k0 + bkq];
            rb1 = *(const float4*)&W[(size_t)(o0 + brow + 64) * CCV + k0 + bkq];
        }
        __syncthreads();

#pragma unroll
        for (int kk = 0; kk < 2; ++kk) {
            uint32_t af[2][4], bf[8][2];
            const int k = kk * 8 + lk;
#pragma unroll
            for (int mt = 0; mt < 2; ++mt) {
                const int r = wm + mt * 16 + lr;
                af[mt][0] = __float_as_uint(Ab[k * 136 + r]);
                af[mt][1] = __float_as_uint(Ab[k * 136 + r + 8]);
                af[mt][2] = __float_as_uint(Ab[(k + 4) * 136 + r]);
                af[mt][3] = __float_as_uint(Ab[(k + 4) * 136 + r + 8]);
            }
#pragma unroll
            for (int nt = 0; nt < 8; ++nt) {
                const int n = wn + nt * 8 + lr;
                bf[nt][0] = __float_as_uint(Bb[n * STRD + k]);
                bf[nt][1] = __float_as_uint(Bb[n * STRD + k + 4]);
            }
#pragma unroll
            for (int mt = 0; mt < 2; ++mt)
#pragma unroll
                for (int nt = 0; nt < 8; ++nt)
                    mma16n8k8(acc[mt][nt], af[mt], bf[nt]);
        }
    }

    // epilogue: register Z-gather + bias + store + BN partials
    float2 sp[8], qp[8];
#pragma unroll
    for (int nt = 0; nt < 8; ++nt) { sp[nt] = make_float2(0.f, 0.f); qp[nt] = make_float2(0.f, 0.f); }
    const float* zb = g_z + (size_t)b * SS * 256;
#pragma unroll
    for (int mt = 0; mt < 2; ++mt) {
        const int rl0 = wm + mt * 16 + lr;
        const int s00 = sidx[rl0 * 3], s01 = sidx[rl0 * 3 + 1], s02 = sidx[rl0 * 3 + 2];
        const float wa0 = swgt[rl0 * 3], wa1 = swgt[rl0 * 3 + 1], wa2 = swgt[rl0 * 3 + 2];
        const int rl1 = rl0 + 8;
        const int s10 = sidx[rl1 * 3], s11 = sidx[rl1 * 3 + 1], s12 = sidx[rl1 * 3 + 2];
        const float wb0 = swgt[rl1 * 3], wb1 = swgt[rl1 * 3 + 1], wb2 = swgt[rl1 * 3 + 2];
        const int r0 = j0 + rl0;
#pragma unroll
        for (int nt = 0; nt < 8; ++nt) {
            const int col = o0 + wn + nt * 8 + 2 * lk;
            float2 za0 = *(const float2*)(zb + (size_t)s00 * 256 + col);
            float2 za1 = *(const float2*)(zb + (size_t)s01 * 256 + col);
            float2 za2 = *(const float2*)(zb + (size_t)s02 * 256 + col);
            float2 zc0 = *(const float2*)(zb + (size_t)s10 * 256 + col);
            float2 zc1 = *(const float2*)(zb + (size_t)s11 * 256 + col);
            float2 zc2 = *(const float2*)(zb + (size_t)s12 * 256 + col);
            float z0x = wa0 * za0.x + wa1 * za1.x + wa2 * za2.x;
            float z0y = wa0 * za0.y + wa1 * za1.y + wa2 * za2.y;
            float z1x = wb0 * zc0.x + wb1 * zc1.x + wb2 * zc2.x;
            float z1y = wb0 * zc0.y + wb1 * zc1.y + wb2 * zc2.y;
            const float b0 = bias[col], b1 = bias[col + 1];
            float v00 = acc[mt][nt][0] + b0 + z0x, v01 = acc[mt][nt][1] + b1 + z0y;
            float v10 = acc[mt][nt][2] + b0 + z1x, v11 = acc[mt][nt][3] + b1 + z1y;
            *(float2*)(out + (size_t)r0 * 256 + col)       = make_float2(v00, v01);
            *(float2*)(out + (size_t)(r0 + 8) * 256 + col) = make_float2(v10, v11);
            sp[nt].x += v00 + v10; sp[nt].y += v01 + v11;
            qp[nt].x += v00 * v00 + v10 * v10; qp[nt].y += v01 * v01 + v11 * v11;
        }
    }
#pragma unroll
    for (int nt = 0; nt < 8; ++nt) {
#pragma unroll
        for (int off = 16; off >= 4; off >>= 1) {
            sp[nt].x += __shfl_xor_sync(0xffffffffu, sp[nt].x, off);
            sp[nt].y += __shfl_xor_sync(0xffffffffu, sp[nt].y, off);
            qp[nt].x += __shfl_xor_sync(0xffffffffu, qp[nt].x, off);
            qp[nt].y += __shfl_xor_sync(0xffffffffu, qp[nt].y, off);
        }
    }
    __syncthreads();
    if (lane < 4) {
#pragma unroll
        for (int nt = 0; nt < 8; ++nt) {
            red_s[(wid * 8 + nt) * 4 + lane] = sp[nt];
            red_q[(wid * 8 + nt) * 4 + lane] = qp[nt];
        }
    }
    __syncthreads();
    if (t < 128) {
        const int wnq = t >> 6, nt = (t >> 3) & 7, lkq = (t >> 1) & 3, hf = t & 1;
        float s = 0.f, q = 0.f;
#pragma unroll
        for (int wq = 0; wq < 4; ++wq) {
            const int w = wq * 2 + wnq;
            float2 a = red_s[(w * 8 + nt) * 4 + lkq];
            float2 c2 = red_q[(w * 8 + nt) * 4 + lkq];
            s += hf ? a.y : a.x;
            q += hf ? c2.y : c2.x;
        }
        psum[(size_t)blockIdx.x * 256 + o0 + t] = s;
        psq [(size_t)blockIdx.x * 256 + o0 + t] = q;
    }
}

// ---------------- finalize BN scale/shift ----------------
__global__ void finalize_bn(const float* __restrict__ psum, const float* __restrict__ psq,
                            int C, const float* __restrict__ gamma, const float* __restrict__ beta,
                            float* __restrict__ scale, float* __restrict__ shift) {
    const int o = threadIdx.x;
    if (o >= C) return;
    float s = 0.f, q = 0.f;
    for (int r = 0; r < NRB; ++r) { s += psum[(size_t)r * C + o]; q += psq[(size_t)r * C + o]; }
    const float invn = 1.f / (float)JJ;
    float m = s * invn;
    float var = q * invn - m * m;
    float sc = gamma[o] * rsqrtf(var + 1e-5f);
    scale[o] = sc;
    shift[o] = beta[o] - m * sc;
}

// ---------------- output: BN1+ReLU + transpose to (B,128,N) ----------------
__global__ void output_kernel(float* __restrict__ out) {
    __shared__ float tile[32][33];
    const int b = blockIdx.z;
    const int n0 = blockIdx.x * 32, p0 = blockIdx.y * 32;
    const int tx = threadIdx.x;
    for (int i = threadIdx.y; i < 32; i += 8) {
        int p = p0 + tx, n = n0 + i;
        float v = g_y1[((size_t)b * NN + n) * 128 + p];
        tile[i][tx] = fmaxf(fmaf(v, g_sc1[p], g_sh1[p]), 0.f);
    }
    __syncthreads();
    for (int i = threadIdx.y; i < 32; i += 8)
        out[((size_t)(b * 128) + p0 + i) * NN + n0 + tx] = tile[tx][i];
}

// ---------------- launch ----------------
extern "C" void kernel_launch(void* const* d_in, const int* in_sizes, int n_in,
                              void* d_out, int out_size) {
    const float* xyz1    = (const float*)d_in[0];
    const float* xyz2    = (const float*)d_in[1];
    const float* points1 = (const float*)d_in[2];
    const float* points2 = (const float*)d_in[3];
    const float* w0      = (const float*)d_in[4];
    const float* b0      = (const float*)d_in[5];
    const float* gamma0  = (const float*)d_in[6];
    const float* beta0   = (const float*)d_in[7];
    const float* w1      = (const float*)d_in[8];
    const float* b1      = (const float*)d_in[9];
    const float* gamma1  = (const float*)d_in[10];
    const float* beta1   = (const float*)d_in[11];
    float* out = (float*)d_out;

    float *p2t, *zbuf, *y0, *y1, *p0s, *p0q, *p1s, *p1q, *sc0, *sh0, *sc1, *sh1;
    cudaGetSymbolAddress((void**)&p2t,  g_p2t);
    cudaGetSymbolAddress((void**)&zbuf, g_z);
    cudaGetSymbolAddress((void**)&y0,   g_y0);
    cudaGetSymbolAddress((void**)&y1,   g_y1);
    cudaGetSymbolAddress((void**)&p0s,  g_p0s);
    cudaGetSymbolAddress((void**)&p0q,  g_p0q);
    cudaGetSymbolAddress((void**)&p1s,  g_p1s);
    cudaGetSymbolAddress((void**)&p1q,  g_p1q);
    cudaGetSymbolAddress((void**)&sc0,  g_sc0);
    cudaGetSymbolAddress((void**)&sh0,  g_sh0);
    cudaGetSymbolAddress((void**)&sc1,  g_sc1);
    cudaGetSymbolAddress((void**)&sh1,  g_sh1);

    // 1: knn candidates
    knn_part<<<dim3(NN / 256, BB, KSPLIT), 256>>>(xyz1, xyz2);
    // 2: merge
    knn_merge<<<JJ / 256, 256>>>();
    // 3: transpose points2 (tf32-rounded)
    transpose_p2<<<dim3(SS / 32, C2V / 32, BB), dim3(32, 8)>>>(points2);
    // 4 (profiled): Z = p2t @ W0b^T
    gemm_pm<256, 256, 1, false, false, false><<<dim3(JZ / 64, 4), 256>>>(
        p2t, w0 + 128, CCV, nullptr, zbuf, nullptr, nullptr, nullptr, nullptr);
    // 5: y0 = T(points1) @ W0a^T + b0 + gather(Z), + BN partials
    gemm0_kernel<<<dim3(NRB, 2), 256>>>(points1, w0, b0, y0, p0s, p0q);
    // 6: BN0 finalize
    finalize_bn<<<1, 256>>>(p0s, p0q, 256, gamma0, beta0, sc0, sh0);
    // 7: y1 = relu(bn0(y0)) @ W1^T + b1, + BN partials
    gemm_pm<256, 128, 2, true, true, true><<<dim3(NRB, 2), 256>>>(
        y0, w1, 256, b1, y1, sc0, sh0, p1s, p1q);
    // 8: BN1 finalize
    finalize_bn<<<1, 128>>>(p1s, p1q, 128, gamma1, beta1, sc1, sh1);
    // 9: output transpose + BN1 + ReLU
    output_kernel<<<dim3(NN / 32, 128 / 32, BB), dim3(32, 8)>>>(out);
}

// round 12
// speedup vs baseline: 1.1204x; 1.0450x over previous
#include <cuda_runtime.h>
#include <cstdint>

#define BB 4
#define NN 8192
#define SS 2048
#define C1V 128
#define C2V 256
#define CCV 384
#define JJ (BB*NN)        // 32768
#define JZ (BB*SS)        // 8192
#define NRB (JJ/128)      // 256
#define KSPLIT 4
#define SCHUNK (SS/KSPLIT)  // 512

// ---------------- device scratch ----------------
__device__ float g_p2t[(size_t)JZ*C2V];            // points2 transposed, tf32-rounded
__device__ float g_z[(size_t)JZ*256];              // Z = p2t @ W0b^T
__device__ float g_w0t[256*CCV];                   // tf32-rounded w0
__device__ float g_w1t[128*256];                   // tf32-rounded w1
__device__ float g_kd[KSPLIT*JJ*3];
__device__ int   g_ki[KSPLIT*JJ*3];
__device__ int   g_idx[JJ*3];
__device__ float g_wgt[JJ*3];
__device__ float g_y0[(size_t)JJ*256];
__device__ float g_y1[(size_t)JJ*128];
__device__ float g_p0s[NRB*256], g_p0q[NRB*256];
__device__ float g_p1s[NRB*128], g_p1q[NRB*128];
__device__ float g_sc0[256], g_sh0[256];
__device__ float g_sc1[128], g_sh1[128];

// ---------------- helpers ----------------
__device__ __forceinline__ uint32_t f2tf32(float x) {
    uint32_t r;
    asm("cvt.rna.tf32.f32 %0, %1;" : "=r"(r) : "f"(x));
    return r;
}
__device__ __forceinline__ float rtf(float x) { return __uint_as_float(f2tf32(x)); }
__device__ __forceinline__ void mma16n8k8(float* c, const uint32_t* a, const uint32_t* b) {
    asm volatile(
        "mma.sync.aligned.m16n8k8.row.col.f32.tf32.tf32.f32 "
        "{%0,%1,%2,%3}, {%4,%5,%6,%7}, {%8,%9}, {%0,%1,%2,%3};"
        : "+f"(c[0]), "+f"(c[1]), "+f"(c[2]), "+f"(c[3])
        : "r"(a[0]), "r"(a[1]), "r"(a[2]), "r"(a[3]), "r"(b[0]), "r"(b[1]));
}
__device__ __forceinline__ void cp16(float* smem, const float* gmem) {
    uint32_t sa = (uint32_t)__cvta_generic_to_shared(smem);
    asm volatile("cp.async.ca.shared.global [%0], [%1], 16;" :: "r"(sa), "l"(gmem));
}

// ---------------- K0: pre-round weights to tf32 ----------------
__global__ void prep_w(const float* __restrict__ w0, const float* __restrict__ w1) {
    int i = blockIdx.x * 256 + threadIdx.x;
    if (i < 256 * CCV) g_w0t[i] = rtf(w0[i]);
    if (i < 128 * 256) g_w1t[i] = rtf(w1[i]);
}

// ---------------- K1: 3-NN over one S-chunk ----------------
__global__ void knn_part(const float* __restrict__ xyz1, const float* __restrict__ xyz2) {
    __shared__ float4 pts[SCHUNK];
    const int b = blockIdx.y, half = blockIdx.z, soff = half * SCHUNK;
    const float* x2 = xyz2 + (size_t)b * 3 * SS + soff;
    for (int s = threadIdx.x; s < SCHUNK; s += blockDim.x) {
        float x = x2[s], y = x2[SS + s], z = x2[2 * SS + s];
        pts[s] = make_float4(x, y, z, x * x + y * y + z * z);
    }
    __syncthreads();
    const int n = blockIdx.x * blockDim.x + threadIdx.x;
    const float* x1 = xyz1 + (size_t)b * 3 * NN;
    const float qx = x1[n], qy = x1[NN + n], qz = x1[2 * NN + n];
    const float qn = qx * qx + qy * qy + qz * qz;
    float d0 = 3.4e38f, d1 = 3.4e38f, d2 = 3.4e38f;
    int   i0 = 0, i1 = 0, i2 = 0;
#pragma unroll 4
    for (int s = 0; s < SCHUNK; ++s) {
        float4 p = pts[s];
        float dot = fmaf(qx, p.x, fmaf(qy, p.y, qz * p.z));
        float d = fmaf(-2.f, dot, qn + p.w);
        if (d < d2) {
            if (d < d1) {
                d2 = d1; i2 = i1;
                if (d < d0) { d1 = d0; i1 = i0; d0 = d; i0 = s; }
                else        { d1 = d;  i1 = s; }
            } else { d2 = d; i2 = s; }
        }
    }
    const int j = b * NN + n;
    const size_t o = ((size_t)half * JJ + j) * 3;
    g_kd[o + 0] = d0; g_kd[o + 1] = d1; g_kd[o + 2] = d2;
    g_ki[o + 0] = soff + i0; g_ki[o + 1] = soff + i1; g_ki[o + 2] = soff + i2;
}

// ---------------- K1b: merge candidate lists + weights ----------------
__global__ void knn_merge() {
    const int j = blockIdx.x * 256 + threadIdx.x;
    float md0 = 3.4e38f, md1 = 3.4e38f, md2 = 3.4e38f;
    int   mi0 = 0, mi1 = 0, mi2 = 0;
#pragma unroll
    for (int h = 0; h < KSPLIT; ++h) {
        const size_t o = ((size_t)h * JJ + j) * 3;
#pragma unroll
        for (int m = 0; m < 3; ++m) {
            float d = g_kd[o + m];
            int   i = g_ki[o + m];
            if (d < md2) {
                if (d < md1) {
                    md2 = md1; mi2 = mi1;
                    if (d < md0) { md1 = md0; mi1 = mi0; md0 = d; mi0 = i; }
                    else         { md1 = d;  mi1 = i; }
                } else { md2 = d; mi2 = i; }
            }
        }
    }
    float r0 = 1.f / (md0 + 1e-8f), r1 = 1.f / (md1 + 1e-8f), r2 = 1.f / (md2 + 1e-8f);
    float inv = 1.f / (r0 + r1 + r2);
    g_idx[j * 3 + 0] = mi0; g_idx[j * 3 + 1] = mi1; g_idx[j * 3 + 2] = mi2;
    g_wgt[j * 3 + 0] = r0 * inv; g_wgt[j * 3 + 1] = r1 * inv; g_wgt[j * 3 + 2] = r2 * inv;
}

// ---------------- K2: points2 (B,C2,S) -> (B*S, C2), tf32-rounded ----------------
__global__ void transpose_p2(const float* __restrict__ src) {
    __shared__ float tile[32][33];
    const int b = blockIdx.z;
    const int l0 = blockIdx.x * 32, c0 = blockIdx.y * 32;
    for (int i = threadIdx.y; i < 32; i += 8)
        tile[i][threadIdx.x] = src[((size_t)b * C2V + c0 + i) * SS + l0 + threadIdx.x];
    __syncthreads();
    for (int i = threadIdx.y; i < 32; i += 8)
        g_p2t[((size_t)b * SS + l0 + i) * C2V + c0 + threadIdx.x] = rtf(tile[threadIdx.x][i]);
}

#define STRD 20

// ======== Z GEMM: Z = p2t @ W0b^T, 64x64 tile, 3-stage cp.async pipeline ========
__global__ __launch_bounds__(256) void gemmz_kernel(
    const float* __restrict__ A, const float* __restrict__ W, float* __restrict__ out)
{
    __shared__ float As[3][64 * STRD];
    __shared__ float Bs[3][64 * STRD];

    const int t = threadIdx.x, wid = t >> 5, lane = t & 31;
    const int j0 = blockIdx.x * 64, o0 = blockIdx.y * 64;
    const int wm = (wid >> 1) * 16, wn = (wid & 1) * 32;
    const int lr = lane >> 2, lk = lane & 3;
    const int arow = t >> 2, akq = (t & 3) * 4;

    float acc[4][4];
#pragma unroll
    for (int nt = 0; nt < 4; ++nt)
#pragma unroll
        for (int i = 0; i < 4; ++i) acc[nt][i] = 0.f;

    const float* ag = A + (size_t)(j0 + arow) * 256 + akq;
    const float* wg = W + (size_t)(o0 + arow) * CCV + akq;

#pragma unroll
    for (int s = 0; s < 2; ++s) {
        cp16(&As[s][arow * STRD + akq], ag + s * 16);
        cp16(&Bs[s][arow * STRD + akq], wg + s * 16);
        asm volatile("cp.async.commit_group;" ::: "memory");
    }

    for (int c = 0; c < 16; ++c) {
        asm volatile("cp.async.wait_group 1;" ::: "memory");
        __syncthreads();
        if (c + 2 < 16) {
            const int s = (c + 2) % 3;
            cp16(&As[s][arow * STRD + akq], ag + (c + 2) * 16);
            cp16(&Bs[s][arow * STRD + akq], wg + (c + 2) * 16);
        }
        asm volatile("cp.async.commit_group;" ::: "memory");

        const float* Ab = As[c % 3];
        const float* Bb = Bs[c % 3];
#pragma unroll
        for (int kk = 0; kk < 2; ++kk) {
            uint32_t af[4], bf[4][2];
            const int k = kk * 8 + lk;
            const int r = wm + lr;
            af[0] = __float_as_uint(Ab[r * STRD + k]);
            af[1] = __float_as_uint(Ab[(r + 8) * STRD + k]);
            af[2] = __float_as_uint(Ab[r * STRD + k + 4]);
            af[3] = __float_as_uint(Ab[(r + 8) * STRD + k + 4]);
#pragma unroll
            for (int nt = 0; nt < 4; ++nt) {
                const int n = wn + nt * 8 + lr;
                bf[nt][0] = __float_as_uint(Bb[n * STRD + k]);
                bf[nt][1] = __float_as_uint(Bb[n * STRD + k + 4]);
            }
#pragma unroll
            for (int nt = 0; nt < 4; ++nt)
                mma16n8k8(acc[nt], af, bf[nt]);
        }
    }
    asm volatile("cp.async.wait_group 0;" ::: "memory");

    const int r0 = j0 + wm + lr;
#pragma unroll
    for (int nt = 0; nt < 4; ++nt) {
        const int col = o0 + wn + nt * 8 + 2 * lk;
        *(float2*)(out + (size_t)r0 * 256 + col)       = make_float2(acc[nt][0], acc[nt][1]);
        *(float2*)(out + (size_t)(r0 + 8) * 256 + col) = make_float2(acc[nt][2], acc[nt][3]);
    }
}

// ======== GEMM0: 128x128 tile, K=128; y0 = T(points1)@W0a^T + b0 + gather(Z) ========
__global__ __launch_bounds__(256) void gemm0_kernel(
    const float* __restrict__ P1, const float* __restrict__ W,
    const float* __restrict__ bias, float* __restrict__ out,
    float* __restrict__ psum, float* __restrict__ psq)
{
    __shared__ float As[2][16 * 136];     // [k][row]
    __shared__ float Bs[2][128 * STRD];
    __shared__ float2 red_s[8 * 32], red_q[8 * 32];
    __shared__ int   sidx[128 * 3];
    __shared__ float swgt[128 * 3];

    const int t = threadIdx.x, wid = t >> 5, lane = t & 31;
    const int j0 = blockIdx.x * 128, o0 = blockIdx.y * 128;
    const int b = j0 >> 13, n0 = j0 & (NN - 1);
    const int wm = (wid >> 1) * 32, wn = (wid & 1) * 64;
    const int lr = lane >> 2, lk = lane & 3;

    if (t < 128) {
#pragma unroll
        for (int m = 0; m < 3; ++m) sidx[t * 3 + m] = g_idx[(size_t)(j0 + t) * 3 + m];
    } else {
        int r = t - 128;
#pragma unroll
        for (int m = 0; m < 3; ++m) swgt[r * 3 + m] = g_wgt[(size_t)(j0 + r) * 3 + m];
    }

    const int cA = t >> 4, gA = t & 15;
    const int brow = t >> 2, bkq = (t & 3) * 4;

    float acc[2][8][4];
#pragma unroll
    for (int mt = 0; mt < 2; ++mt)
#pragma unroll
        for (int nt = 0; nt < 8; ++nt)
#pragma unroll
            for (int i = 0; i < 4; ++i) acc[mt][nt][i] = 0.f;

    float4 ra0, ra1, rb0, rb1;
    {
        const float* ap = P1 + ((size_t)b * C1V + cA) * NN + n0 + gA * 4;
        ra0 = *(const float4*)ap;
        ra1 = *(const float4*)(ap + 64);
        rb0 = *(const float4*)&W[(size_t)(o0 + brow) * CCV + bkq];
        rb1 = *(const float4*)&W[(size_t)(o0 + brow + 64) * CCV + bkq];
    }
    __syncthreads();

    constexpr int NCHUNK = 8;
    for (int c = 0; c < NCHUNK; ++c) {
        float* Ab = As[c & 1];
        float* Bb = Bs[c & 1];
        uint4 u0, u1;
        u0.x = f2tf32(ra0.x); u0.y = f2tf32(ra0.y); u0.z = f2tf32(ra0.z); u0.w = f2tf32(ra0.w);
        u1.x = f2tf32(ra1.x); u1.y = f2tf32(ra1.y); u1.z = f2tf32(ra1.z); u1.w = f2tf32(ra1.w);
        *(uint4*)&Ab[cA * 136 + gA * 4]      = u0;
        *(uint4*)&Ab[cA * 136 + 64 + gA * 4] = u1;
        *(float4*)&Bb[brow * STRD + bkq]        = rb0;   // W already tf32-rounded
        *(float4*)&Bb[(brow + 64) * STRD + bkq] = rb1;

        if (c + 1 < NCHUNK) {
            const int k0 = (c + 1) * 16;
            const float* ap = P1 + ((size_t)b * C1V + k0 + cA) * NN + n0 + gA * 4;
            ra0 = *(const float4*)ap;
            ra1 = *(const float4*)(ap + 64);
            rb0 = *(const float4*)&W[(size_t)(o0 + brow) * CCV + k0 + bkq];
            rb1 = *(const float4*)&W[(size_t)(o0 + brow + 64) * CCV + k0 + bkq];
        }
        __syncthreads();

#pragma unroll
        for (int kk = 0; kk < 2; ++kk) {
            uint32_t af[2][4], bf[8][2];
            const int k = kk * 8 + lk;
#pragma unroll
            for (int mt = 0; mt < 2; ++mt) {
                const int r = wm + mt * 16 + lr;
                af[mt][0] = __float_as_uint(Ab[k * 136 + r]);
                af[mt][1] = __float_as_uint(Ab[k * 136 + r + 8]);
                af[mt][2] = __float_as_uint(Ab[(k + 4) * 136 + r]);
                af[mt][3] = __float_as_uint(Ab[(k + 4) * 136 + r + 8]);
            }
#pragma unroll
            for (int nt = 0; nt < 8; ++nt) {
                const int n = wn + nt * 8 + lr;
                bf[nt][0] = __float_as_uint(Bb[n * STRD + k]);
                bf[nt][1] = __float_as_uint(Bb[n * STRD + k + 4]);
            }
#pragma unroll
            for (int mt = 0; mt < 2; ++mt)
#pragma unroll
                for (int nt = 0; nt < 8; ++nt)
                    mma16n8k8(acc[mt][nt], af[mt], bf[nt]);
        }
    }

    // epilogue: register Z-gather + bias + store + BN partials
    float2 sp[8], qp[8];
#pragma unroll
    for (int nt = 0; nt < 8; ++nt) { sp[nt] = make_float2(0.f, 0.f); qp[nt] = make_float2(0.f, 0.f); }
    const float* zb = g_z + (size_t)b * SS * 256;
#pragma unroll
    for (int mt = 0; mt < 2; ++mt) {
        const int rl0 = wm + mt * 16 + lr;
        const int s00 = sidx[rl0 * 3], s01 = sidx[rl0 * 3 + 1], s02 = sidx[rl0 * 3 + 2];
        const float wa0 = swgt[rl0 * 3], wa1 = swgt[rl0 * 3 + 1], wa2 = swgt[rl0 * 3 + 2];
        const int rl1 = rl0 + 8;
        const int s10 = sidx[rl1 * 3], s11 = sidx[rl1 * 3 + 1], s12 = sidx[rl1 * 3 + 2];
        const float wb0 = swgt[rl1 * 3], wb1 = swgt[rl1 * 3 + 1], wb2 = swgt[rl1 * 3 + 2];
        const int r0 = j0 + rl0;
#pragma unroll
        for (int nt = 0; nt < 8; ++nt) {
            const int col = o0 + wn + nt * 8 + 2 * lk;
            float2 za0 = *(const float2*)(zb + (size_t)s00 * 256 + col);
            float2 za1 = *(const float2*)(zb + (size_t)s01 * 256 + col);
            float2 za2 = *(const float2*)(zb + (size_t)s02 * 256 + col);
            float2 zc0 = *(const float2*)(zb + (size_t)s10 * 256 + col);
            float2 zc1 = *(const float2*)(zb + (size_t)s11 * 256 + col);
            float2 zc2 = *(const float2*)(zb + (size_t)s12 * 256 + col);
            float z0x = wa0 * za0.x + wa1 * za1.x + wa2 * za2.x;
            float z0y = wa0 * za0.y + wa1 * za1.y + wa2 * za2.y;
            float z1x = wb0 * zc0.x + wb1 * zc1.x + wb2 * zc2.x;
            float z1y = wb0 * zc0.y + wb1 * zc1.y + wb2 * zc2.y;
            const float b0 = bias[col], b1 = bias[col + 1];
            float v00 = acc[mt][nt][0] + b0 + z0x, v01 = acc[mt][nt][1] + b1 + z0y;
            float v10 = acc[mt][nt][2] + b0 + z1x, v11 = acc[mt][nt][3] + b1 + z1y;
            *(float2*)(out + (size_t)r0 * 256 + col)       = make_float2(v00, v01);
            *(float2*)(out + (size_t)(r0 + 8) * 256 + col) = make_float2(v10, v11);
            sp[nt].x += v00 + v10; sp[nt].y += v01 + v11;
            qp[nt].x += v00 * v00 + v10 * v10; qp[nt].y += v01 * v01 + v11 * v11;
        }
    }
#pragma unroll
    for (int nt = 0; nt < 8; ++nt) {
#pragma unroll
        for (int off = 16; off >= 4; off >>= 1) {
            sp[nt].x += __shfl_xor_sync(0xffffffffu, sp[nt].x, off);
            sp[nt].y += __shfl_xor_sync(0xffffffffu, sp[nt].y, off);
            qp[nt].x += __shfl_xor_sync(0xffffffffu, qp[nt].x, off);
            qp[nt].y += __shfl_xor_sync(0xffffffffu, qp[nt].y, off);
        }
    }
    __syncthreads();
    if (lane < 4) {
#pragma unroll
        for (int nt = 0; nt < 8; ++nt) {
            red_s[(wid * 8 + nt) * 4 + lane] = sp[nt];
            red_q[(wid * 8 + nt) * 4 + lane] = qp[nt];
        }
    }
    __syncthreads();
    if (t < 128) {
        const int wnq = t >> 6, nt = (t >> 3) & 7, lkq = (t >> 1) & 3, hf = t & 1;
        float s = 0.f, q = 0.f;
#pragma unroll
        for (int wq = 0; wq < 4; ++wq) {
            const int w = wq * 2 + wnq;
            float2 a = red_s[(w * 8 + nt) * 4 + lkq];
            float2 c2 = red_q[(w * 8 + nt) * 4 + lkq];
            s += hf ? a.y : a.x;
            q += hf ? c2.y : c2.x;
        }
        psum[(size_t)blockIdx.x * 256 + o0 + t] = s;
        psq [(size_t)blockIdx.x * 256 + o0 + t] = q;
    }
}

// ======== GEMM1: 128x128 tile, K=256; y1 = relu(bn0(y0)) @ W1^T + b1, + BN partials ========
__global__ __launch_bounds__(256) void gemm1_kernel(
    const float* __restrict__ A, const float* __restrict__ W,
    const float* __restrict__ bias, float* __restrict__ out,
    const float* __restrict__ scale, const float* __restrict__ shift,
    float* __restrict__ psum, float* __restrict__ psq)
{
    __shared__ float As[2][128 * STRD];
    __shared__ float Bs[2][128 * STRD];
    __shared__ float2 red_s[8 * 32], red_q[8 * 32];
    __shared__ float ssc[256], ssh[256];

    const int t = threadIdx.x, wid = t >> 5, lane = t & 31;
    const int j0 = blockIdx.x * 128;
    const int wm = (wid >> 1) * 32, wn = (wid & 1) * 64;
    const int lr = lane >> 2, lk = lane & 3;

    ssc[t] = scale[t]; ssh[t] = shift[t];
    __syncthreads();

    const int arow = t >> 2, akq = (t & 3) * 4;

    float acc[2][8][4];
#pragma unroll
    for (int mt = 0; mt < 2; ++mt)
#pragma unroll
        for (int nt = 0; nt < 8; ++nt)
#pragma unroll
            for (int i = 0; i < 4; ++i) acc[mt][nt][i] = 0.f;

    float4 pa0, pa1, rb0, rb1;
    {
        const float* a0 = A + (size_t)(j0 + arow) * 256 + akq;
        pa0 = *(const float4*)a0;
        pa1 = *(const float4*)(a0 + (size_t)64 * 256);
        rb0 = *(const float4*)&W[(size_t)arow * 256 + akq];
        rb1 = *(const float4*)&W[(size_t)(arow + 64) * 256 + akq];
    }

    constexpr int NCHUNK = 16;
    for (int c = 0; c < NCHUNK; ++c) {
        float* Ab = As[c & 1];
        float* Bb = Bs[c & 1];
        float4 va0 = pa0, va1 = pa1;
        {
            const int kb = c * 16 + akq;
            float s0 = ssc[kb], s1 = ssc[kb+1], s2 = ssc[kb+2], s3 = ssc[kb+3];
            float h0 = ssh[kb], h1 = ssh[kb+1], h2 = ssh[kb+2], h3 = ssh[kb+3];
            va0.x = rtf(fmaxf(fmaf(va0.x, s0, h0), 0.f));
            va0.y = rtf(fmaxf(fmaf(va0.y, s1, h1), 0.f));
            va0.z = rtf(fmaxf(fmaf(va0.z, s2, h2), 0.f));
            va0.w = rtf(fmaxf(fmaf(va0.w, s3, h3), 0.f));
            va1.x = rtf(fmaxf(fmaf(va1.x, s0, h0), 0.f));
            va1.y = rtf(fmaxf(fmaf(va1.y, s1, h1), 0.f));
            va1.z = rtf(fmaxf(fmaf(va1.z, s2, h2), 0.f));
            va1.w = rtf(fmaxf(fmaf(va1.w, s3, h3), 0.f));
        }
        *(float4*)&Ab[arow * STRD + akq]        = va0;
        *(float4*)&Ab[(arow + 64) * STRD + akq] = va1;
        *(float4*)&Bb[arow * STRD + akq]        = rb0;
        *(float4*)&Bb[(arow + 64) * STRD + akq] = rb1;

        if (c + 1 < NCHUNK) {
            const int k0 = (c + 1) * 16;
            const float* a0 = A + (size_t)(j0 + arow) * 256 + k0 + akq;
            pa0 = *(const float4*)a0;
            pa1 = *(const float4*)(a0 + (size_t)64 * 256);
            rb0 = *(const float4*)&W[(size_t)arow * 256 + k0 + akq];
            rb1 = *(const float4*)&W[(size_t)(arow + 64) * 256 + k0 + akq];
        }
        __syncthreads();

#pragma unroll
        for (int kk = 0; kk < 2; ++kk) {
            uint32_t af[2][4], bf[8][2];
            const int k = kk * 8 + lk;
#pragma unroll
            for (int mt = 0; mt < 2; ++mt) {
                const int r = wm + mt * 16 + lr;
                af[mt][0] = __float_as_uint(Ab[r * STRD + k]);
                af[mt][1] = __float_as_uint(Ab[(r + 8) * STRD + k]);
                af[mt][2] = __float_as_uint(Ab[r * STRD + k + 4]);
                af[mt][3] = __float_as_uint(Ab[(r + 8) * STRD + k + 4]);
            }
#pragma unroll
            for (int nt = 0; nt < 8; ++nt) {
                const int n = wn + nt * 8 + lr;
                bf[nt][0] = __float_as_uint(Bb[n * STRD + k]);
                bf[nt][1] = __float_as_uint(Bb[n * STRD + k + 4]);
            }
#pragma unroll
            for (int mt = 0; mt < 2; ++mt)
#pragma unroll
                for (int nt = 0; nt < 8; ++nt)
                    mma16n8k8(acc[mt][nt], af[mt], bf[nt]);
        }
    }

    float2 sp[8], qp[8];
#pragma unroll
    for (int nt = 0; nt < 8; ++nt) { sp[nt] = make_float2(0.f, 0.f); qp[nt] = make_float2(0.f, 0.f); }
#pragma unroll
    for (int mt = 0; mt < 2; ++mt) {
        const int r0 = j0 + wm + mt * 16 + lr;
#pragma unroll
        for (int nt = 0; nt < 8; ++nt) {
            const int col = wn + nt * 8 + 2 * lk;
            const float b0 = bias[col], b1 = bias[col + 1];
            float v00 = acc[mt][nt][0] + b0, v01 = acc[mt][nt][1] + b1;
            float v10 = acc[mt][nt][2] + b0, v11 = acc[mt][nt][3] + b1;
            *(float2*)(out + (size_t)r0 * 128 + col)       = make_float2(v00, v01);
            *(float2*)(out + (size_t)(r0 + 8) * 128 + col) = make_float2(v10, v11);
            sp[nt].x += v00 + v10; sp[nt].y += v01 + v11;
            qp[nt].x += v00 * v00 + v10 * v10; qp[nt].y += v01 * v01 + v11 * v11;
        }
    }
#pragma unroll
    for (int nt = 0; nt < 8; ++nt) {
#pragma unroll
        for (int off = 16; off >= 4; off >>= 1) {
            sp[nt].x += __shfl_xor_sync(0xffffffffu, sp[nt].x, off);
            sp[nt].y += __shfl_xor_sync(0xffffffffu, sp[nt].y, off);
            qp[nt].x += __shfl_xor_sync(0xffffffffu, qp[nt].x, off);
            qp[nt].y += __shfl_xor_sync(0xffffffffu, qp[nt].y, off);
        }
    }
    __syncthreads();
    if (lane < 4) {
#pragma unroll
        for (int nt = 0; nt < 8; ++nt) {
            red_s[(wid * 8 + nt) * 4 + lane] = sp[nt];
            red_q[(wid * 8 + nt) * 4 + lane] = qp[nt];
        }
    }
    __syncthreads();
    if (t < 128) {
        const int wnq = t >> 6, nt = (t >> 3) & 7, lkq = (t >> 1) & 3, hf = t & 1;
        float s = 0.f, q = 0.f;
#pragma unroll
        for (int wq = 0; wq < 4; ++wq) {
            const int w = wq * 2 + wnq;
            float2 a = red_s[(w * 8 + nt) * 4 + lkq];
            float2 c2 = red_q[(w * 8 + nt) * 4 + lkq];
            s += hf ? a.y : a.x;
            q += hf ? c2.y : c2.x;
        }
        psum[(size_t)blockIdx.x * 128 + t] = s;
        psq [(size_t)blockIdx.x * 128 + t] = q;
    }
}

// ---------------- finalize BN scale/shift ----------------
__global__ void finalize_bn(const float* __restrict__ psum, const float* __restrict__ psq,
                            int C, const float* __restrict__ gamma, const float* __restrict__ beta,
                            float* __restrict__ scale, float* __restrict__ shift) {
    const int o = threadIdx.x;
    if (o >= C) return;
    float s = 0.f, q = 0.f;
    for (int r = 0; r < NRB; ++r) { s += psum[(size_t)r * C + o]; q += psq[(size_t)r * C + o]; }
    const float invn = 1.f / (float)JJ;
    float m = s * invn;
    float var = q * invn - m * m;
    float sc = gamma[o] * rsqrtf(var + 1e-5f);
    scale[o] = sc;
    shift[o] = beta[o] - m * sc;
}

// ---------------- output: BN1+ReLU + transpose to (B,128,N) ----------------
__global__ void output_kernel(float* __restrict__ out) {
    __shared__ float tile[32][33];
    const int b = blockIdx.z;
    const int n0 = blockIdx.x * 32, p0 = blockIdx.y * 32;
    const int tx = threadIdx.x;
    for (int i = threadIdx.y; i < 32; i += 8) {
        int p = p0 + tx, n = n0 + i;
        float v = g_y1[((size_t)b * NN + n) * 128 + p];
        tile[i][tx] = fmaxf(fmaf(v, g_sc1[p], g_sh1[p]), 0.f);
    }
    __syncthreads();
    for (int i = threadIdx.y; i < 32; i += 8)
        out[((size_t)(b * 128) + p0 + i) * NN + n0 + tx] = tile[tx][i];
}

// ---------------- launch ----------------
extern "C" void kernel_launch(void* const* d_in, const int* in_sizes, int n_in,
                              void* d_out, int out_size) {
    const float* xyz1    = (const float*)d_in[0];
    const float* xyz2    = (const float*)d_in[1];
    const float* points1 = (const float*)d_in[2];
    const float* points2 = (const float*)d_in[3];
    const float* w0      = (const float*)d_in[4];
    const float* b0      = (const float*)d_in[5];
    const float* gamma0  = (const float*)d_in[6];
    const float* beta0   = (const float*)d_in[7];
    const float* w1      = (const float*)d_in[8];
    const float* b1      = (const float*)d_in[9];
    const float* gamma1  = (const float*)d_in[10];
    const float* beta1   = (const float*)d_in[11];
    float* out = (float*)d_out;

    float *p2t, *zbuf, *w0t, *w1t, *y0, *y1, *p0s, *p0q, *p1s, *p1q, *sc0, *sh0, *sc1, *sh1;
    cudaGetSymbolAddress((void**)&p2t,  g_p2t);
    cudaGetSymbolAddress((void**)&zbuf, g_z);
    cudaGetSymbolAddress((void**)&w0t,  g_w0t);
    cudaGetSymbolAddress((void**)&w1t,  g_w1t);
    cudaGetSymbolAddress((void**)&y0,   g_y0);
    cudaGetSymbolAddress((void**)&y1,   g_y1);
    cudaGetSymbolAddress((void**)&p0s,  g_p0s);
    cudaGetSymbolAddress((void**)&p0q,  g_p0q);
    cudaGetSymbolAddress((void**)&p1s,  g_p1s);
    cudaGetSymbolAddress((void**)&p1q,  g_p1q);
    cudaGetSymbolAddress((void**)&sc0,  g_sc0);
    cudaGetSymbolAddress((void**)&sh0,  g_sh0);
    cudaGetSymbolAddress((void**)&sc1,  g_sc1);
    cudaGetSymbolAddress((void**)&sh1,  g_sh1);

    // 1: pre-round weights
    prep_w<<<CCV, 256>>>(w0, w1);
    // 2: knn candidates
    knn_part<<<dim3(NN / 256, BB, KSPLIT), 256>>>(xyz1, xyz2);
    // 3: merge
    knn_merge<<<JJ / 256, 256>>>();
    // 4: transpose points2 (tf32-rounded)
    transpose_p2<<<dim3(SS / 32, C2V / 32, BB), dim3(32, 8)>>>(points2);
    // 5: Z = p2t @ W0b^T  (cp.async 3-stage)
    gemmz_kernel<<<dim3(JZ / 64, 4), 256>>>(p2t, w0t + 128, zbuf);
    // 6: y0 = T(points1) @ W0a^T + b0 + gather(Z), + BN partials
    gemm0_kernel<<<dim3(NRB, 2), 256>>>(points1, w0t, b0, y0, p0s, p0q);
    // 7: BN0 finalize
    finalize_bn<<<1, 256>>>(p0s, p0q, 256, gamma0, beta0, sc0, sh0);
    // 8: y1 = relu(bn0(y0)) @ W1^T + b1, + BN partials
    gemm1_kernel<<<NRB, 256>>>(y0, w1t, b1, y1, sc0, sh0, p1s, p1q);
    // 9: BN1 finalize
    finalize_bn<<<1, 128>>>(p1s, p1q, 128, gamma1, beta1, sc1, sh1);
    // 10: output transpose + BN1 + ReLU
    output_kernel<<<dim3(NN / 32, 128 / 32, BB), dim3(32, 8)>>>(out);
}

// round 13
// speedup vs baseline: 1.1613x; 1.0366x over previous
#include <cuda_runtime.h>
#include <cstdint>

#define BB 4
#define NN 8192
#define SS 2048
#define C1V 128
#define C2V 256
#define CCV 384
#define JJ (BB*NN)        // 32768
#define JZ (BB*SS)        // 8192
#define NRB (JJ/128)      // 256
#define KSPLIT 4
#define SCHUNK (SS/KSPLIT)  // 512

// ---------------- device scratch ----------------
__device__ float g_z[(size_t)JZ*256];              // Z = p2t @ W0b^T
__device__ float g_w0t[256*CCV];                   // tf32-rounded w0
__device__ float g_w1t[128*256];                   // tf32-rounded w1
__device__ float g_kd[KSPLIT*JJ*3];
__device__ int   g_ki[KSPLIT*JJ*3];
__device__ int   g_idx[JJ*3];
__device__ float g_wgt[JJ*3];
__device__ float g_y0[(size_t)JJ*256];
__device__ float g_y1[(size_t)JJ*128];
__device__ float g_p0s[NRB*256], g_p0q[NRB*256];
__device__ float g_p1s[NRB*128], g_p1q[NRB*128];
__device__ float g_sc0[256], g_sh0[256];
__device__ float g_sc1[128], g_sh1[128];

// ---------------- helpers ----------------
__device__ __forceinline__ uint32_t f2tf32(float x) {
    uint32_t r;
    asm("cvt.rna.tf32.f32 %0, %1;" : "=r"(r) : "f"(x));
    return r;
}
__device__ __forceinline__ float rtf(float x) { return __uint_as_float(f2tf32(x)); }
__device__ __forceinline__ void mma16n8k8(float* c, const uint32_t* a, const uint32_t* b) {
    asm volatile(
        "mma.sync.aligned.m16n8k8.row.col.f32.tf32.tf32.f32 "
        "{%0,%1,%2,%3}, {%4,%5,%6,%7}, {%8,%9}, {%0,%1,%2,%3};"
        : "+f"(c[0]), "+f"(c[1]), "+f"(c[2]), "+f"(c[3])
        : "r"(a[0]), "r"(a[1]), "r"(a[2]), "r"(a[3]), "r"(b[0]), "r"(b[1]));
}
__device__ __forceinline__ void cp16(float* smem, const float* gmem) {
    uint32_t sa = (uint32_t)__cvta_generic_to_shared(smem);
    asm volatile("cp.async.ca.shared.global [%0], [%1], 16;" :: "r"(sa), "l"(gmem));
}
#define CP_COMMIT() asm volatile("cp.async.commit_group;" ::: "memory")
#define CP_WAIT1()  asm volatile("cp.async.wait_group 1;" ::: "memory")
#define CP_WAIT0()  asm volatile("cp.async.wait_group 0;" ::: "memory")

// ---------------- K0: pre-round weights to tf32 ----------------
__global__ void prep_w(const float* __restrict__ w0, const float* __restrict__ w1) {
    int i = blockIdx.x * 256 + threadIdx.x;
    if (i < 256 * CCV) g_w0t[i] = rtf(w0[i]);
    if (i < 128 * 256) g_w1t[i] = rtf(w1[i]);
}

// ---------------- K1: 3-NN over one S-chunk ----------------
__global__ void knn_part(const float* __restrict__ xyz1, const float* __restrict__ xyz2) {
    __shared__ float4 pts[SCHUNK];
    const int b = blockIdx.y, half = blockIdx.z, soff = half * SCHUNK;
    const float* x2 = xyz2 + (size_t)b * 3 * SS + soff;
    for (int s = threadIdx.x; s < SCHUNK; s += blockDim.x) {
        float x = x2[s], y = x2[SS + s], z = x2[2 * SS + s];
        pts[s] = make_float4(x, y, z, x * x + y * y + z * z);
    }
    __syncthreads();
    const int n = blockIdx.x * blockDim.x + threadIdx.x;
    const float* x1 = xyz1 + (size_t)b * 3 * NN;
    const float qx = x1[n], qy = x1[NN + n], qz = x1[2 * NN + n];
    const float qn = qx * qx + qy * qy + qz * qz;
    float d0 = 3.4e38f, d1 = 3.4e38f, d2 = 3.4e38f;
    int   i0 = 0, i1 = 0, i2 = 0;
#pragma unroll 4
    for (int s = 0; s < SCHUNK; ++s) {
        float4 p = pts[s];
        float dot = fmaf(qx, p.x, fmaf(qy, p.y, qz * p.z));
        float d = fmaf(-2.f, dot, qn + p.w);
        if (d < d2) {
            if (d < d1) {
                d2 = d1; i2 = i1;
                if (d < d0) { d1 = d0; i1 = i0; d0 = d; i0 = s; }
                else        { d1 = d;  i1 = s; }
            } else { d2 = d; i2 = s; }
        }
    }
    const int j = b * NN + n;
    const size_t o = ((size_t)half * JJ + j) * 3;
    g_kd[o + 0] = d0; g_kd[o + 1] = d1; g_kd[o + 2] = d2;
    g_ki[o + 0] = soff + i0; g_ki[o + 1] = soff + i1; g_ki[o + 2] = soff + i2;
}

// ---------------- K1b: merge candidate lists + weights ----------------
__global__ void knn_merge() {
    const int j = blockIdx.x * 256 + threadIdx.x;
    float md0 = 3.4e38f, md1 = 3.4e38f, md2 = 3.4e38f;
    int   mi0 = 0, mi1 = 0, mi2 = 0;
#pragma unroll
    for (int h = 0; h < KSPLIT; ++h) {
        const size_t o = ((size_t)h * JJ + j) * 3;
#pragma unroll
        for (int m = 0; m < 3; ++m) {
            float d = g_kd[o + m];
            int   i = g_ki[o + m];
            if (d < md2) {
                if (d < md1) {
                    md2 = md1; mi2 = mi1;
                    if (d < md0) { md1 = md0; mi1 = mi0; md0 = d; mi0 = i; }
                    else         { md1 = d;  mi1 = i; }
                } else { md2 = d; mi2 = i; }
            }
        }
    }
    float r0 = 1.f / (md0 + 1e-8f), r1 = 1.f / (md1 + 1e-8f), r2 = 1.f / (md2 + 1e-8f);
    float inv = 1.f / (r0 + r1 + r2);
    g_idx[j * 3 + 0] = mi0; g_idx[j * 3 + 1] = mi1; g_idx[j * 3 + 2] = mi2;
    g_wgt[j * 3 + 0] = r0 * inv; g_wgt[j * 3 + 1] = r1 * inv; g_wgt[j * 3 + 2] = r2 * inv;
}

#define STRD 20

// ======== Z GEMM: Z = T(points2) @ W0b^T, 64x64 tile, K=256 ========
// Fused transpose A-loader (channel-major points2, k-major smem), 3-stage cp.async B.
__global__ __launch_bounds__(256) void gemmz_kernel(
    const float* __restrict__ P2, const float* __restrict__ W, float* __restrict__ out)
{
    __shared__ float As[2][16 * 72];     // [k][row], stride 72: (8k+r)%32 conflict-free
    __shared__ float Bs[3][64 * STRD];

    const int t = threadIdx.x, wid = t >> 5, lane = t & 31;
    const int bz = blockIdx.x >> 5;            // batch
    const int s0 = (blockIdx.x & 31) * 64;     // point offset within batch
    const int o0 = blockIdx.y * 64;
    const int wm = (wid >> 1) * 16, wn = (wid & 1) * 32;
    const int lr = lane >> 2, lk = lane & 3;
    const int cA = t >> 4, gA = t & 15;        // A: channel cA, points gA*4..+3
    const int brow = t >> 2, bkq = (t & 3) * 4;

    float acc[4][4];
#pragma unroll
    for (int nt = 0; nt < 4; ++nt)
#pragma unroll
        for (int i = 0; i < 4; ++i) acc[nt][i] = 0.f;

    const float* wg = W + (size_t)(o0 + brow) * CCV + bkq;   // W pre-offset to col 128
    const float* ab = P2 + ((size_t)bz * C2V + cA) * SS + s0 + gA * 4;

    cp16(&Bs[0][brow * STRD + bkq], wg);        CP_COMMIT();
    cp16(&Bs[1][brow * STRD + bkq], wg + 16);   CP_COMMIT();
    float4 ra = *(const float4*)ab;

    constexpr int NC = 16;   // K = 256
    for (int c = 0; c < NC; ++c) {
        uint4 u;
        u.x = f2tf32(ra.x); u.y = f2tf32(ra.y); u.z = f2tf32(ra.z); u.w = f2tf32(ra.w);
        *(uint4*)&As[c & 1][cA * 72 + gA * 4] = u;
        if (c + 1 < NC) ra = *(const float4*)(ab + (size_t)(c + 1) * 16 * SS);
        CP_WAIT1();
        __syncthreads();
        if (c + 2 < NC) cp16(&Bs[(c + 2) % 3][brow * STRD + bkq], wg + (c + 2) * 16);
        CP_COMMIT();

        const float* Ab = As[c & 1];
        const float* Bb = Bs[c % 3];
#pragma unroll
        for (int kk = 0; kk < 2; ++kk) {
            uint32_t af[4], bf[4][2];
            const int k = kk * 8 + lk;
            const int r = wm + lr;
            af[0] = __float_as_uint(Ab[k * 72 + r]);
            af[1] = __float_as_uint(Ab[k * 72 + r + 8]);
            af[2] = __float_as_uint(Ab[(k + 4) * 72 + r]);
            af[3] = __float_as_uint(Ab[(k + 4) * 72 + r + 8]);
#pragma unroll
            for (int nt = 0; nt < 4; ++nt) {
                const int n = wn + nt * 8 + lr;
                bf[nt][0] = __float_as_uint(Bb[n * STRD + k]);
                bf[nt][1] = __float_as_uint(Bb[n * STRD + k + 4]);
            }
#pragma unroll
            for (int nt = 0; nt < 4; ++nt)
                mma16n8k8(acc[nt], af, bf[nt]);
        }
    }
    CP_WAIT0();

    const int r0 = s0 + wm + lr;
#pragma unroll
    for (int nt = 0; nt < 4; ++nt) {
        const int col = o0 + wn + nt * 8 + 2 * lk;
        float* orow = out + ((size_t)bz * SS + r0) * 256 + col;
        *(float2*)orow              = make_float2(acc[nt][0], acc[nt][1]);
        *(float2*)(orow + 8 * 256)  = make_float2(acc[nt][2], acc[nt][3]);
    }
}

// ======== GEMM0: 128x128 tile, K=128; y0 = T(points1)@W0a^T + b0 + gather(Z) ========
__global__ __launch_bounds__(256) void gemm0_kernel(
    const float* __restrict__ P1, const float* __restrict__ W,
    const float* __restrict__ bias, float* __restrict__ out,
    float* __restrict__ psum, float* __restrict__ psq)
{
    __shared__ float As[2][16 * 136];     // [k][row]
    __shared__ float Bs[2][128 * STRD];
    __shared__ float2 red_s[8 * 32], red_q[8 * 32];
    __shared__ int   sidx[128 * 3];
    __shared__ float swgt[128 * 3];

    const int t = threadIdx.x, wid = t >> 5, lane = t & 31;
    const int j0 = blockIdx.x * 128, o0 = blockIdx.y * 128;
    const int b = j0 >> 13, n0 = j0 & (NN - 1);
    const int wm = (wid >> 1) * 32, wn = (wid & 1) * 64;
    const int lr = lane >> 2, lk = lane & 3;

    if (t < 128) {
#pragma unroll
        for (int m = 0; m < 3; ++m) sidx[t * 3 + m] = g_idx[(size_t)(j0 + t) * 3 + m];
    } else {
        int r = t - 128;
#pragma unroll
        for (int m = 0; m < 3; ++m) swgt[r * 3 + m] = g_wgt[(size_t)(j0 + r) * 3 + m];
    }

    const int cA = t >> 4, gA = t & 15;
    const int brow = t >> 2, bkq = (t & 3) * 4;

    float acc[2][8][4];
#pragma unroll
    for (int mt = 0; mt < 2; ++mt)
#pragma unroll
        for (int nt = 0; nt < 8; ++nt)
#pragma unroll
            for (int i = 0; i < 4; ++i) acc[mt][nt][i] = 0.f;

    float4 ra0, ra1, rb0, rb1;
    {
        const float* ap = P1 + ((size_t)b * C1V + cA) * NN + n0 + gA * 4;
        ra0 = *(const float4*)ap;
        ra1 = *(const float4*)(ap + 64);
        rb0 = *(const float4*)&W[(size_t)(o0 + brow) * CCV + bkq];
        rb1 = *(const float4*)&W[(size_t)(o0 + brow + 64) * CCV + bkq];
    }
    __syncthreads();

    constexpr int NCHUNK = 8;
    for (int c = 0; c < NCHUNK; ++c) {
        float* Ab = As[c & 1];
        float* Bb = Bs[c & 1];
        uint4 u0, u1;
        u0.x = f2tf32(ra0.x); u0.y = f2tf32(ra0.y); u0.z = f2tf32(ra0.z); u0.w = f2tf32(ra0.w);
        u1.x = f2tf32(ra1.x); u1.y = f2tf32(ra1.y); u1.z = f2tf32(ra1.z); u1.w = f2tf32(ra1.w);
        *(uint4*)&Ab[cA * 136 + gA * 4]      = u0;
        *(uint4*)&Ab[cA * 136 + 64 + gA * 4] = u1;
        *(float4*)&Bb[brow * STRD + bkq]        = rb0;
        *(float4*)&Bb[(brow + 64) * STRD + bkq] = rb1;

        if (c + 1 < NCHUNK) {
            const int k0 = (c + 1) * 16;
            const float* ap = P1 + ((size_t)b * C1V + k0 + cA) * NN + n0 + gA * 4;
            ra0 = *(const float4*)ap;
            ra1 = *(const float4*)(ap + 64);
            rb0 = *(const float4*)&W[(size_t)(o0 + brow) * CCV + k0 + bkq];
            rb1 = *(const float4*)&W[(size_t)(o0 + brow + 64) * CCV + k0 + bkq];
        }
        __syncthreads();

#pragma unroll
        for (int kk = 0; kk < 2; ++kk) {
            uint32_t af[2][4], bf[8][2];
            const int k = kk * 8 + lk;
#pragma unroll
            for (int mt = 0; mt < 2; ++mt) {
                const int r = wm + mt * 16 + lr;
                af[mt][0] = __float_as_uint(Ab[k * 136 + r]);
                af[mt][1] = __float_as_uint(Ab[k * 136 + r + 8]);
                af[mt][2] = __float_as_uint(Ab[(k + 4) * 136 + r]);
                af[mt][3] = __float_as_uint(Ab[(k + 4) * 136 + r + 8]);
            }
#pragma unroll
            for (int nt = 0; nt < 8; ++nt) {
                const int n = wn + nt * 8 + lr;
                bf[nt][0] = __float_as_uint(Bb[n * STRD + k]);
                bf[nt][1] = __float_as_uint(Bb[n * STRD + k + 4]);
            }
#pragma unroll
            for (int mt = 0; mt < 2; ++mt)
#pragma unroll
                for (int nt = 0; nt < 8; ++nt)
                    mma16n8k8(acc[mt][nt], af[mt], bf[nt]);
        }
    }

    // epilogue: register Z-gather + bias + store + BN partials
    float2 sp[8], qp[8];
#pragma unroll
    for (int nt = 0; nt < 8; ++nt) { sp[nt] = make_float2(0.f, 0.f); qp[nt] = make_float2(0.f, 0.f); }
    const float* zb = g_z + (size_t)b * SS * 256;
#pragma unroll
    for (int mt = 0; mt < 2; ++mt) {
        const int rl0 = wm + mt * 16 + lr;
        const int s00 = sidx[rl0 * 3], s01 = sidx[rl0 * 3 + 1], s02 = sidx[rl0 * 3 + 2];
        const float wa0 = swgt[rl0 * 3], wa1 = swgt[rl0 * 3 + 1], wa2 = swgt[rl0 * 3 + 2];
        const int rl1 = rl0 + 8;
        const int s10 = sidx[rl1 * 3], s11 = sidx[rl1 * 3 + 1], s12 = sidx[rl1 * 3 + 2];
        const float wb0 = swgt[rl1 * 3], wb1 = swgt[rl1 * 3 + 1], wb2 = swgt[rl1 * 3 + 2];
        const int r0 = j0 + rl0;
#pragma unroll
        for (int nt = 0; nt < 8; ++nt) {
            const int col = o0 + wn + nt * 8 + 2 * lk;
            float2 za0 = *(const float2*)(zb + (size_t)s00 * 256 + col);
            float2 za1 = *(const float2*)(zb + (size_t)s01 * 256 + col);
            float2 za2 = *(const float2*)(zb + (size_t)s02 * 256 + col);
            float2 zc0 = *(const float2*)(zb + (size_t)s10 * 256 + col);
            float2 zc1 = *(const float2*)(zb + (size_t)s11 * 256 + col);
            float2 zc2 = *(const float2*)(zb + (size_t)s12 * 256 + col);
            float z0x = wa0 * za0.x + wa1 * za1.x + wa2 * za2.x;
            float z0y = wa0 * za0.y + wa1 * za1.y + wa2 * za2.y;
            float z1x = wb0 * zc0.x + wb1 * zc1.x + wb2 * zc2.x;
            float z1y = wb0 * zc0.y + wb1 * zc1.y + wb2 * zc2.y;
            const float b0 = bias[col], b1 = bias[col + 1];
            float v00 = acc[mt][nt][0] + b0 + z0x, v01 = acc[mt][nt][1] + b1 + z0y;
            float v10 = acc[mt][nt][2] + b0 + z1x, v11 = acc[mt][nt][3] + b1 + z1y;
            *(float2*)(out + (size_t)r0 * 256 + col)       = make_float2(v00, v01);
            *(float2*)(out + (size_t)(r0 + 8) * 256 + col) = make_float2(v10, v11);
            sp[nt].x += v00 + v10; sp[nt].y += v01 + v11;
            qp[nt].x += v00 * v00 + v10 * v10; qp[nt].y += v01 * v01 + v11 * v11;
        }
    }
#pragma unroll
    for (int nt = 0; nt < 8; ++nt) {
#pragma unroll
        for (int off = 16; off >= 4; off >>= 1) {
            sp[nt].x += __shfl_xor_sync(0xffffffffu, sp[nt].x, off);
            sp[nt].y += __shfl_xor_sync(0xffffffffu, sp[nt].y, off);
            qp[nt].x += __shfl_xor_sync(0xffffffffu, qp[nt].x, off);
            qp[nt].y += __shfl_xor_sync(0xffffffffu, qp[nt].y, off);
        }
    }
    __syncthreads();
    if (lane < 4) {
#pragma unroll
        for (int nt = 0; nt < 8; ++nt) {
            red_s[(wid * 8 + nt) * 4 + lane] = sp[nt];
            red_q[(wid * 8 + nt) * 4 + lane] = qp[nt];
        }
    }
    __syncthreads();
    if (t < 128) {
        const int wnq = t >> 6, nt = (t >> 3) & 7, lkq = (t >> 1) & 3, hf = t & 1;
        float s = 0.f, q = 0.f;
#pragma unroll
        for (int wq = 0; wq < 4; ++wq) {
            const int w = wq * 2 + wnq;
            float2 a = red_s[(w * 8 + nt) * 4 + lkq];
            float2 c2 = red_q[(w * 8 + nt) * 4 + lkq];
            s += hf ? a.y : a.x;
            q += hf ? c2.y : c2.x;
        }
        psum[(size_t)blockIdx.x * 256 + o0 + t] = s;
        psq [(size_t)blockIdx.x * 256 + o0 + t] = q;
    }
}

// ======== GEMM1: 128x128 tile, K=256; dynamic smem, cp.async B 3-stage ========
// dyn layout (floats): As[0, 5120) 2x128x20, Bs[5120, 12800) 3x128x20,
//   ssc[12800,13056), ssh[13056,13312), red_s/red_q float2 [13312+] (2x256 float2)
#define G1_SMEM ((13312 + 4 * 256) * 4)
__global__ __launch_bounds__(256) void gemm1_kernel(
    const float* __restrict__ A, const float* __restrict__ W,
    const float* __restrict__ bias, float* __restrict__ out,
    const float* __restrict__ scale, const float* __restrict__ shift,
    float* __restrict__ psum, float* __restrict__ psq)
{
    extern __shared__ float dyn[];
    float* As0 = dyn;
    float* Bs0 = dyn + 5120;
    float* ssc = dyn + 12800;
    float* ssh = dyn + 13056;
    float2* red_s = (float2*)(dyn + 13312);
    float2* red_q = red_s + 256;

    const int t = threadIdx.x, wid = t >> 5, lane = t & 31;
    const int j0 = blockIdx.x * 128;
    const int wm = (wid >> 1) * 32, wn = (wid & 1) * 64;
    const int lr = lane >> 2, lk = lane & 3;

    ssc[t] = scale[t]; ssh[t] = shift[t];

    const int arow = t >> 2, akq = (t & 3) * 4;

    float acc[2][8][4];
#pragma unroll
    for (int mt = 0; mt < 2; ++mt)
#pragma unroll
        for (int nt = 0; nt < 8; ++nt)
#pragma unroll
            for (int i = 0; i < 4; ++i) acc[mt][nt][i] = 0.f;

    const float* wg0 = W + (size_t)arow * 256 + akq;
    const float* wg1 = W + (size_t)(arow + 64) * 256 + akq;
    cp16(&Bs0[0 * 2560 + arow * STRD + akq], wg0);
    cp16(&Bs0[0 * 2560 + (arow + 64) * STRD + akq], wg1);
    CP_COMMIT();
    cp16(&Bs0[1 * 2560 + arow * STRD + akq], wg0 + 16);
    cp16(&Bs0[1 * 2560 + (arow + 64) * STRD + akq], wg1 + 16);
    CP_COMMIT();

    float4 pa0, pa1;
    {
        const float* a0 = A + (size_t)(j0 + arow) * 256 + akq;
        pa0 = *(const float4*)a0;
        pa1 = *(const float4*)(a0 + (size_t)64 * 256);
    }
    __syncthreads();   // ssc/ssh ready

    constexpr int NCHUNK = 16;
    for (int c = 0; c < NCHUNK; ++c) {
        float* Ab = As0 + (c & 1) * 2560;
        float4 va0 = pa0, va1 = pa1;
        {
            const int kb = c * 16 + akq;
            float s0 = ssc[kb], s1 = ssc[kb+1], s2 = ssc[kb+2], s3 = ssc[kb+3];
            float h0 = ssh[kb], h1 = ssh[kb+1], h2 = ssh[kb+2], h3 = ssh[kb+3];
            va0.x = rtf(fmaxf(fmaf(va0.x, s0, h0), 0.f));
            va0.y = rtf(fmaxf(fmaf(va0.y, s1, h1), 0.f));
            va0.z = rtf(fmaxf(fmaf(va0.z, s2, h2), 0.f));
            va0.w = rtf(fmaxf(fmaf(va0.w, s3, h3), 0.f));
            va1.x = rtf(fmaxf(fmaf(va1.x, s0, h0), 0.f));
            va1.y = rtf(fmaxf(fmaf(va1.y, s1, h1), 0.f));
            va1.z = rtf(fmaxf(fmaf(va1.z, s2, h2), 0.f));
            va1.w = rtf(fmaxf(fmaf(va1.w, s3, h3), 0.f));
        }
        *(float4*)&Ab[arow * STRD + akq]        = va0;
        *(float4*)&Ab[(arow + 64) * STRD + akq] = va1;

        if (c + 1 < NCHUNK) {
            const int k0 = (c + 1) * 16;
            const float* a0 = A + (size_t)(j0 + arow) * 256 + k0 + akq;
            pa0 = *(const float4*)a0;
            pa1 = *(const float4*)(a0 + (size_t)64 * 256);
        }
        CP_WAIT1();
        __syncthreads();
        if (c + 2 < NCHUNK) {
            cp16(&Bs0[((c + 2) % 3) * 2560 + arow * STRD + akq], wg0 + (c + 2) * 16);
            cp16(&Bs0[((c + 2) % 3) * 2560 + (arow + 64) * STRD + akq], wg1 + (c + 2) * 16);
        }
        CP_COMMIT();

        const float* Bb = Bs0 + (c % 3) * 2560;
#pragma unroll
        for (int kk = 0; kk < 2; ++kk) {
            uint32_t af[2][4], bf[8][2];
            const int k = kk * 8 + lk;
#pragma unroll
            for (int mt = 0; mt < 2; ++mt) {
                const int r = wm + mt * 16 + lr;
                af[mt][0] = __float_as_uint(Ab[r * STRD + k]);
                af[mt][1] = __float_as_uint(Ab[(r + 8) * STRD + k]);
                af[mt][2] = __float_as_uint(Ab[r * STRD + k + 4]);
                af[mt][3] = __float_as_uint(Ab[(r + 8) * STRD + k + 4]);
            }
#pragma unroll
            for (int nt = 0; nt < 8; ++nt) {
                const int n = wn + nt * 8 + lr;
                bf[nt][0] = __float_as_uint(Bb[n * STRD + k]);
                bf[nt][1] = __float_as_uint(Bb[n * STRD + k + 4]);
            }
#pragma unroll
            for (int mt = 0; mt < 2; ++mt)
#pragma unroll
                for (int nt = 0; nt < 8; ++nt)
                    mma16n8k8(acc[mt][nt], af[mt], bf[nt]);
        }
    }
    CP_WAIT0();

    float2 sp[8], qp[8];
#pragma unroll
    for (int nt = 0; nt < 8; ++nt) { sp[nt] = make_float2(0.f, 0.f); qp[nt] = make_float2(0.f, 0.f); }
#pragma unroll
    for (int mt = 0; mt < 2; ++mt) {
        const int r0 = j0 + wm + mt * 16 + lr;
#pragma unroll
        for (int nt = 0; nt < 8; ++nt) {
            const int col = wn + nt * 8 + 2 * lk;
            const float b0 = bias[col], b1 = bias[col + 1];
            float v00 = acc[mt][nt][0] + b0, v01 = acc[mt][nt][1] + b1;
            float v10 = acc[mt][nt][2] + b0, v11 = acc[mt][nt][3] + b1;
            *(float2*)(out + (size_t)r0 * 128 + col)       = make_float2(v00, v01);
            *(float2*)(out + (size_t)(r0 + 8) * 128 + col) = make_float2(v10, v11);
            sp[nt].x += v00 + v10; sp[nt].y += v01 + v11;
            qp[nt].x += v00 * v00 + v10 * v10; qp[nt].y += v01 * v01 + v11 * v11;
        }
    }
#pragma unroll
    for (int nt = 0; nt < 8; ++nt) {
#pragma unroll
        for (int off = 16; off >= 4; off >>= 1) {
            sp[nt].x += __shfl_xor_sync(0xffffffffu, sp[nt].x, off);
            sp[nt].y += __shfl_xor_sync(0xffffffffu, sp[nt].y, off);
            qp[nt].x += __shfl_xor_sync(0xffffffffu, qp[nt].x, off);
            qp[nt].y += __shfl_xor_sync(0xffffffffu, qp[nt].y, off);
        }
    }
    __syncthreads();
    if (lane < 4) {
#pragma unroll
        for (int nt = 0; nt < 8; ++nt) {
            red_s[(wid * 8 + nt) * 4 + lane] = sp[nt];
            red_q[(wid * 8 + nt) * 4 + lane] = qp[nt];
        }
    }
    __syncthreads();
    if (t < 128) {
        const int wnq = t >> 6, nt = (t >> 3) & 7, lkq = (t >> 1) & 3, hf = t & 1;
        float s = 0.f, q = 0.f;
#pragma unroll
        for (int wq = 0; wq < 4; ++wq) {
            const int w = wq * 2 + wnq;
            float2 a = red_s[(w * 8 + nt) * 4 + lkq];
            float2 c2 = red_q[(w * 8 + nt) * 4 + lkq];
            s += hf ? a.y : a.x;
            q += hf ? c2.y : c2.x;
        }
        psum[(size_t)blockIdx.x * 128 + t] = s;
        psq [(size_t)blockIdx.x * 128 + t] = q;
    }
}

// ---------------- finalize BN scale/shift ----------------
__global__ void finalize_bn(const float* __restrict__ psum, const float* __restrict__ psq,
                            int C, const float* __restrict__ gamma, const float* __restrict__ beta,
                            float* __restrict__ scale, float* __restrict__ shift) {
    const int o = threadIdx.x;
    if (o >= C) return;
    float s = 0.f, q = 0.f;
    for (int r = 0; r < NRB; ++r) { s += psum[(size_t)r * C + o]; q += psq[(size_t)r * C + o]; }
    const float invn = 1.f / (float)JJ;
    float m = s * invn;
    float var = q * invn - m * m;
    float sc = gamma[o] * rsqrtf(var + 1e-5f);
    scale[o] = sc;
    shift[o] = beta[o] - m * sc;
}

// ---------------- output: BN1+ReLU + transpose to (B,128,N) ----------------
__global__ void output_kernel(float* __restrict__ out) {
    __shared__ float tile[32][33];
    const int b = blockIdx.z;
    const int n0 = blockIdx.x * 32, p0 = blockIdx.y * 32;
    const int tx = threadIdx.x;
    for (int i = threadIdx.y; i < 32; i += 8) {
        int p = p0 + tx, n = n0 + i;
        float v = g_y1[((size_t)b * NN + n) * 128 + p];
        tile[i][tx] = fmaxf(fmaf(v, g_sc1[p], g_sh1[p]), 0.f);
    }
    __syncthreads();
    for (int i = threadIdx.y; i < 32; i += 8)
        out[((size_t)(b * 128) + p0 + i) * NN + n0 + tx] = tile[tx][i];
}

// ---------------- launch ----------------
extern "C" void kernel_launch(void* const* d_in, const int* in_sizes, int n_in,
                              void* d_out, int out_size) {
    const float* xyz1    = (const float*)d_in[0];
    const float* xyz2    = (const float*)d_in[1];
    const float* points1 = (const float*)d_in[2];
    const float* points2 = (const float*)d_in[3];
    const float* w0      = (const float*)d_in[4];
    const float* b0      = (const float*)d_in[5];
    const float* gamma0  = (const float*)d_in[6];
    const float* beta0   = (const float*)d_in[7];
    const float* w1      = (const float*)d_in[8];
    const float* b1      = (const float*)d_in[9];
    const float* gamma1  = (const float*)d_in[10];
    const float* beta1   = (const float*)d_in[11];
    float* out = (float*)d_out;

    float *zbuf, *w0t, *w1t, *y0, *y1, *p0s, *p0q, *p1s, *p1q, *sc0, *sh0, *sc1, *sh1;
    cudaGetSymbolAddress((void**)&zbuf, g_z);
    cudaGetSymbolAddress((void**)&w0t,  g_w0t);
    cudaGetSymbolAddress((void**)&w1t,  g_w1t);
    cudaGetSymbolAddress((void**)&y0,   g_y0);
    cudaGetSymbolAddress((void**)&y1,   g_y1);
    cudaGetSymbolAddress((void**)&p0s,  g_p0s);
    cudaGetSymbolAddress((void**)&p0q,  g_p0q);
    cudaGetSymbolAddress((void**)&p1s,  g_p1s);
    cudaGetSymbolAddress((void**)&p1q,  g_p1q);
    cudaGetSymbolAddress((void**)&sc0,  g_sc0);
    cudaGetSymbolAddress((void**)&sh0,  g_sh0);
    cudaGetSymbolAddress((void**)&sc1,  g_sc1);
    cudaGetSymbolAddress((void**)&sh1,  g_sh1);

    cudaFuncSetAttribute(gemm1_kernel, cudaFuncAttributeMaxDynamicSharedMemorySize, G1_SMEM);

    // 1: pre-round weights
    prep_w<<<CCV, 256>>>(w0, w1);
    // 2: knn candidates
    knn_part<<<dim3(NN / 256, BB, KSPLIT), 256>>>(xyz1, xyz2);
    // 3: merge
    knn_merge<<<JJ / 256, 256>>>();
    // 4 (profiled): Z = T(points2) @ W0b^T, fused transpose loader
    gemmz_kernel<<<dim3(JZ / 64, 4), 256>>>(points2, w0t + 128, zbuf);
    // 5: y0 = T(points1) @ W0a^T + b0 + gather(Z), + BN partials
    gemm0_kernel<<<dim3(NRB, 2), 256>>>(points1, w0t, b0, y0, p0s, p0q);
    // 6: BN0 finalize
    finalize_bn<<<1, 256>>>(p0s, p0q, 256, gamma0, beta0, sc0, sh0);
    // 7: y1 = relu(bn0(y0)) @ W1^T + b1, + BN partials
    gemm1_kernel<<<NRB, 256, G1_SMEM>>>(y0, w1t, b1, y1, sc0, sh0, p1s, p1q);
    // 8: BN1 finalize
    finalize_bn<<<1, 128>>>(p1s, p1q, 128, gamma1, beta1, sc1, sh1);
    // 9: output transpose + BN1 + ReLU
    output_kernel<<<dim3(NN / 32, 128 / 32, BB), dim3(32, 8)>>>(out);
}

// round 15
// speedup vs baseline: 1.1855x; 1.0208x over previous
#include <cuda_runtime.h>
#include <cstdint>

#define BB 4
#define NN 8192
#define SS 2048
#define C1V 128
#define C2V 256
#define CCV 384
#define JJ (BB*NN)        // 32768
#define JZ (BB*SS)        // 8192
#define NRB (JJ/128)      // 256
#define KSPLIT 4
#define SCHUNK (SS/KSPLIT)  // 512

// ---------------- device scratch ----------------
__device__ float g_z[(size_t)JZ*256];              // Z = T(points2) @ W0b^T
__device__ float g_w0t[256*CCV];                   // tf32-rounded w0
__device__ float g_w1t[128*256];                   // tf32-rounded w1
__device__ float g_kd[KSPLIT*JJ*3];
__device__ int   g_ki[KSPLIT*JJ*3];
__device__ int   g_idx[JJ*3];
__device__ float g_wgt[JJ*3];
__device__ float g_y0[(size_t)JJ*256];
__device__ float g_y1[(size_t)JJ*128];
__device__ float g_p0s[NRB*256], g_p0q[NRB*256];
__device__ float g_p1s[NRB*128], g_p1q[NRB*128];
__device__ float g_sc0[256], g_sh0[256];
__device__ float g_sc1[128], g_sh1[128];

// ---------------- helpers ----------------
__device__ __forceinline__ uint32_t f2tf32(float x) {
    uint32_t r;
    asm("cvt.rna.tf32.f32 %0, %1;" : "=r"(r) : "f"(x));
    return r;
}
__device__ __forceinline__ float rtf(float x) { return __uint_as_float(f2tf32(x)); }
__device__ __forceinline__ void mma16n8k8(float* c, const uint32_t* a, const uint32_t* b) {
    asm volatile(
        "mma.sync.aligned.m16n8k8.row.col.f32.tf32.tf32.f32 "
        "{%0,%1,%2,%3}, {%4,%5,%6,%7}, {%8,%9}, {%0,%1,%2,%3};"
        : "+f"(c[0]), "+f"(c[1]), "+f"(c[2]), "+f"(c[3])
        : "r"(a[0]), "r"(a[1]), "r"(a[2]), "r"(a[3]), "r"(b[0]), "r"(b[1]));
}
__device__ __forceinline__ void cp16(float* smem, const float* gmem) {
    uint32_t sa = (uint32_t)__cvta_generic_to_shared(smem);
    asm volatile("cp.async.ca.shared.global [%0], [%1], 16;" :: "r"(sa), "l"(gmem));
}
#define CP_COMMIT() asm volatile("cp.async.commit_group;" ::: "memory")
#define CP_WAIT1()  asm volatile("cp.async.wait_group 1;" ::: "memory")
#define CP_WAIT0()  asm volatile("cp.async.wait_group 0;" ::: "memory")

// ---------------- K0: pre-round weights to tf32 ----------------
__global__ void prep_w(const float* __restrict__ w0, const float* __restrict__ w1) {
    int i = blockIdx.x * 256 + threadIdx.x;
    if (i < 256 * CCV) g_w0t[i] = rtf(w0[i]);
    if (i < 128 * 256) g_w1t[i] = rtf(w1[i]);
}

// ---------------- K1: 3-NN over one S-chunk ----------------
__global__ void knn_part(const float* __restrict__ xyz1, const float* __restrict__ xyz2) {
    __shared__ float4 pts[SCHUNK];
    const int b = blockIdx.y, half = blockIdx.z, soff = half * SCHUNK;
    const float* x2 = xyz2 + (size_t)b * 3 * SS + soff;
    for (int s = threadIdx.x; s < SCHUNK; s += blockDim.x) {
        float x = x2[s], y = x2[SS + s], z = x2[2 * SS + s];
        pts[s] = make_float4(x, y, z, x * x + y * y + z * z);
    }
    __syncthreads();
    const int n = blockIdx.x * blockDim.x + threadIdx.x;
    const float* x1 = xyz1 + (size_t)b * 3 * NN;
    const float qx = x1[n], qy = x1[NN + n], qz = x1[2 * NN + n];
    const float qn = qx * qx + qy * qy + qz * qz;
    float d0 = 3.4e38f, d1 = 3.4e38f, d2 = 3.4e38f;
    int   i0 = 0, i1 = 0, i2 = 0;
#pragma unroll 4
    for (int s = 0; s < SCHUNK; ++s) {
        float4 p = pts[s];
        float dot = fmaf(qx, p.x, fmaf(qy, p.y, qz * p.z));
        float d = fmaf(-2.f, dot, qn + p.w);
        if (d < d2) {
            if (d < d1) {
                d2 = d1; i2 = i1;
                if (d < d0) { d1 = d0; i1 = i0; d0 = d; i0 = s; }
                else        { d1 = d;  i1 = s; }
            } else { d2 = d; i2 = s; }
        }
    }
    const int j = b * NN + n;
    const size_t o = ((size_t)half * JJ + j) * 3;
    g_kd[o + 0] = d0; g_kd[o + 1] = d1; g_kd[o + 2] = d2;
    g_ki[o + 0] = soff + i0; g_ki[o + 1] = soff + i1; g_ki[o + 2] = soff + i2;
}

// ---------------- K1b: merge candidate lists + weights ----------------
__global__ void knn_merge() {
    const int j = blockIdx.x * 256 + threadIdx.x;
    float md0 = 3.4e38f, md1 = 3.4e38f, md2 = 3.4e38f;
    int   mi0 = 0, mi1 = 0, mi2 = 0;
#pragma unroll
    for (int h = 0; h < KSPLIT; ++h) {
        const size_t o = ((size_t)h * JJ + j) * 3;
#pragma unroll
        for (int m = 0; m < 3; ++m) {
            float d = g_kd[o + m];
            int   i = g_ki[o + m];
            if (d < md2) {
                if (d < md1) {
                    md2 = md1; mi2 = mi1;
                    if (d < md0) { md1 = md0; mi1 = mi0; md0 = d; mi0 = i; }
                    else         { md1 = d;  mi1 = i; }
                } else { md2 = d; mi2 = i; }
            }
        }
    }
    float r0 = 1.f / (md0 + 1e-8f), r1 = 1.f / (md1 + 1e-8f), r2 = 1.f / (md2 + 1e-8f);
    float inv = 1.f / (r0 + r1 + r2);
    g_idx[j * 3 + 0] = mi0; g_idx[j * 3 + 1] = mi1; g_idx[j * 3 + 2] = mi2;
    g_wgt[j * 3 + 0] = r0 * inv; g_wgt[j * 3 + 1] = r1 * inv; g_wgt[j * 3 + 2] = r2 * inv;
}

#define STRD 20

// ======== Z GEMM: Z = T(points2) @ W0b^T, 128x64 tile, K=256 ========
// Fused transpose A-loader (gemm0 pattern: k-major As, stride 136), cp.async B 3-stage.
// 8 warps, warp tile 32x32. Grid: (SS/128 per batch * BB) x (256/64) = 64 x 4.
__global__ __launch_bounds__(256) void gemmz_kernel(
    const float* __restrict__ P2, const float* __restrict__ W, float* __restrict__ out)
{
    __shared__ float As[2][16 * 136];    // [k][row], rows 0..127 + pad
    __shared__ float Bs[3][64 * STRD];

    const int t = threadIdx.x, wid = t >> 5, lane = t & 31;
    const int bz = blockIdx.x >> 4;            // batch  (16 row-blocks per batch)
    const int s0 = (blockIdx.x & 15) * 128;    // point offset within batch
    const int o0 = blockIdx.y * 64;
    const int wm = (wid >> 1) * 32, wn = (wid & 1) * 32;
    const int lr = lane >> 2, lk = lane & 3;
    const int cA = t >> 4, gA = t & 15;        // A: channel cA, points gA*4 & +64
    const int brow = t >> 2, bkq = (t & 3) * 4;

    float acc[2][4][4];
#pragma unroll
    for (int mt = 0; mt < 2; ++mt)
#pragma unroll
        for (int nt = 0; nt < 4; ++nt)
#pragma unroll
            for (int i = 0; i < 4; ++i) acc[mt][nt][i] = 0.f;

    const float* wg = W + (size_t)(o0 + brow) * CCV + bkq;   // W pre-offset to col 128
    const float* ab = P2 + ((size_t)bz * C2V + cA) * SS + s0 + gA * 4;

    cp16(&Bs[0][brow * STRD + bkq], wg);        CP_COMMIT();
    cp16(&Bs[1][brow * STRD + bkq], wg + 16);   CP_COMMIT();
    float4 ra0 = *(const float4*)ab;
    float4 ra1 = *(const float4*)(ab + 64);

    constexpr int NC = 16;   // K = 256
    for (int c = 0; c < NC; ++c) {
        uint4 u0, u1;
        u0.x = f2tf32(ra0.x); u0.y = f2tf32(ra0.y); u0.z = f2tf32(ra0.z); u0.w = f2tf32(ra0.w);
        u1.x = f2tf32(ra1.x); u1.y = f2tf32(ra1.y); u1.z = f2tf32(ra1.z); u1.w = f2tf32(ra1.w);
        float* Ab = As[c & 1];
        *(uint4*)&Ab[cA * 136 + gA * 4]      = u0;
        *(uint4*)&Ab[cA * 136 + 64 + gA * 4] = u1;
        if (c + 1 < NC) {
            const float* ap = ab + (size_t)(c + 1) * 16 * SS;
            ra0 = *(const float4*)ap;
            ra1 = *(const float4*)(ap + 64);
        }
        CP_WAIT1();
        __syncthreads();
        if (c + 2 < NC) cp16(&Bs[(c + 2) % 3][brow * STRD + bkq], wg + (c + 2) * 16);
        CP_COMMIT();

        const float* Bb = Bs[c % 3];
#pragma unroll
        for (int kk = 0; kk < 2; ++kk) {
            uint32_t af[2][4], bf[4][2];
            const int k = kk * 8 + lk;
#pragma unroll
            for (int mt = 0; mt < 2; ++mt) {
                const int r = wm + mt * 16 + lr;
                af[mt][0] = __float_as_uint(Ab[k * 136 + r]);
                af[mt][1] = __float_as_uint(Ab[k * 136 + r + 8]);
                af[mt][2] = __float_as_uint(Ab[(k + 4) * 136 + r]);
                af[mt][3] = __float_as_uint(Ab[(k + 4) * 136 + r + 8]);
            }
#pragma unroll
            for (int nt = 0; nt < 4; ++nt) {
                const int n = wn + nt * 8 + lr;
                bf[nt][0] = __float_as_uint(Bb[n * STRD + k]);
                bf[nt][1] = __float_as_uint(Bb[n * STRD + k + 4]);
            }
#pragma unroll
            for (int mt = 0; mt < 2; ++mt)
#pragma unroll
                for (int nt = 0; nt < 4; ++nt)
                    mma16n8k8(acc[mt][nt], af[mt], bf[nt]);
        }
    }
    CP_WAIT0();

#pragma unroll
    for (int mt = 0; mt < 2; ++mt) {
        const int r0 = s0 + wm + mt * 16 + lr;
#pragma unroll
        for (int nt = 0; nt < 4; ++nt) {
            const int col = o0 + wn + nt * 8 + 2 * lk;
            float* orow = out + ((size_t)bz * SS + r0) * 256 + col;
            *(float2*)orow             = make_float2(acc[mt][nt][0], acc[mt][nt][1]);
            *(float2*)(orow + 8 * 256) = make_float2(acc[mt][nt][2], acc[mt][nt][3]);
        }
    }
}

// ======== GEMM0: 128x128 tile, K=128; y0 = T(points1)@W0a^T + b0 + gather(Z) ========
__global__ __launch_bounds__(256) void gemm0_kernel(
    const float* __restrict__ P1, const float* __restrict__ W,
    const float* __restrict__ bias, float* __restrict__ out,
    float* __restrict__ psum, float* __restrict__ psq)
{
    __shared__ float As[2][16 * 136];     // [k][row]
    __shared__ float Bs[2][128 * STRD];
    __shared__ float2 red_s[8 * 32], red_q[8 * 32];
    __shared__ int   sidx[128 * 3];
    __shared__ float swgt[128 * 3];

    const int t = threadIdx.x, wid = t >> 5, lane = t & 31;
    const int j0 = blockIdx.x * 128, o0 = blockIdx.y * 128;
    const int b = j0 >> 13, n0 = j0 & (NN - 1);
    const int wm = (wid >> 1) * 32, wn = (wid & 1) * 64;
    const int lr = lane >> 2, lk = lane & 3;

    if (t < 128) {
#pragma unroll
        for (int m = 0; m < 3; ++m) sidx[t * 3 + m] = g_idx[(size_t)(j0 + t) * 3 + m];
    } else {
        int r = t - 128;
#pragma unroll
        for (int m = 0; m < 3; ++m) swgt[r * 3 + m] = g_wgt[(size_t)(j0 + r) * 3 + m];
    }

    const int cA = t >> 4, gA = t & 15;
    const int brow = t >> 2, bkq = (t & 3) * 4;

    float acc[2][8][4];
#pragma unroll
    for (int mt = 0; mt < 2; ++mt)
#pragma unroll
        for (int nt = 0; nt < 8; ++nt)
#pragma unroll
            for (int i = 0; i < 4; ++i) acc[mt][nt][i] = 0.f;

    float4 ra0, ra1, rb0, rb1;
    {
        const float* ap = P1 + ((size_t)b * C1V + cA) * NN + n0 + gA * 4;
        ra0 = *(const float4*)ap;
        ra1 = *(const float4*)(ap + 64);
        rb0 = *(const float4*)&W[(size_t)(o0 + brow) * CCV + bkq];
        rb1 = *(const float4*)&W[(size_t)(o0 + brow + 64) * CCV + bkq];
    }
    __syncthreads();

    constexpr int NCHUNK = 8;
    for (int c = 0; c < NCHUNK; ++c) {
        float* Ab = As[c & 1];
        float* Bb = Bs[c & 1];
        uint4 u0, u1;
        u0.x = f2tf32(ra0.x); u0.y = f2tf32(ra0.y); u0.z = f2tf32(ra0.z); u0.w = f2tf32(ra0.w);
        u1.x = f2tf32(ra1.x); u1.y = f2tf32(ra1.y); u1.z = f2tf32(ra1.z); u1.w = f2tf32(ra1.w);
        *(uint4*)&Ab[cA * 136 + gA * 4]      = u0;
        *(uint4*)&Ab[cA * 136 + 64 + gA * 4] = u1;
        *(float4*)&Bb[brow * STRD + bkq]        = rb0;
        *(float4*)&Bb[(brow + 64) * STRD + bkq] = rb1;

        if (c + 1 < NCHUNK) {
            const int k0 = (c + 1) * 16;
            const float* ap = P1 + ((size_t)b * C1V + k0 + cA) * NN + n0 + gA * 4;
            ra0 = *(const float4*)ap;
            ra1 = *(const float4*)(ap + 64);
            rb0 = *(const float4*)&W[(size_t)(o0 + brow) * CCV + k0 + bkq];
            rb1 = *(const float4*)&W[(size_t)(o0 + brow + 64) * CCV + k0 + bkq];
        }
        __syncthreads();

#pragma unroll
        for (int kk = 0; kk < 2; ++kk) {
            uint32_t af[2][4], bf[8][2];
            const int k = kk * 8 + lk;
#pragma unroll
            for (int mt = 0; mt < 2; ++mt) {
                const int r = wm + mt * 16 + lr;
                af[mt][0] = __float_as_uint(Ab[k * 136 + r]);
                af[mt][1] = __float_as_uint(Ab[k * 136 + r + 8]);
                af[mt][2] = __float_as_uint(Ab[(k + 4) * 136 + r]);
                af[mt][3] = __float_as_uint(Ab[(k + 4) * 136 + r + 8]);
            }
#pragma unroll
            for (int nt = 0; nt < 8; ++nt) {
                const int n = wn + nt * 8 + lr;
                bf[nt][0] = __float_as_uint(Bb[n * STRD + k]);
                bf[nt][1] = __float_as_uint(Bb[n * STRD + k + 4]);
            }
#pragma unroll
            for (int mt = 0; mt < 2; ++mt)
#pragma unroll
                for (int nt = 0; nt < 8; ++nt)
                    mma16n8k8(acc[mt][nt], af[mt], bf[nt]);
        }
    }

    // epilogue: register Z-gather + bias + store + BN partials
    float2 sp[8], qp[8];
#pragma unroll
    for (int nt = 0; nt < 8; ++nt) { sp[nt] = make_float2(0.f, 0.f); qp[nt] = make_float2(0.f, 0.f); }
    const float* zb = g_z + (size_t)b * SS * 256;
#pragma unroll
    for (int mt = 0; mt < 2; ++mt) {
        const int rl0 = wm + mt * 16 + lr;
        const int s00 = sidx[rl0 * 3], s01 = sidx[rl0 * 3 + 1], s02 = sidx[rl0 * 3 + 2];
        const float wa0 = swgt[rl0 * 3], wa1 = swgt[rl0 * 3 + 1], wa2 = swgt[rl0 * 3 + 2];
        const int rl1 = rl0 + 8;
        const int s10 = sidx[rl1 * 3], s11 = sidx[rl1 * 3 + 1], s12 = sidx[rl1 * 3 + 2];
        const float wb0 = swgt[rl1 * 3], wb1 = swgt[rl1 * 3 + 1], wb2 = swgt[rl1 * 3 + 2];
        const int r0 = j0 + rl0;
#pragma unroll
        for (int nt = 0; nt < 8; ++nt) {
            const int col = o0 + wn + nt * 8 + 2 * lk;
            float2 za0 = *(const float2*)(zb + (size_t)s00 * 256 + col);
            float2 za1 = *(const float2*)(zb + (size_t)s01 * 256 + col);
            float2 za2 = *(const float2*)(zb + (size_t)s02 * 256 + col);
            float2 zc0 = *(const float2*)(zb + (size_t)s10 * 256 + col);
            float2 zc1 = *(const float2*)(zb + (size_t)s11 * 256 + col);
            float2 zc2 = *(const float2*)(zb + (size_t)s12 * 256 + col);
            float z0x = wa0 * za0.x + wa1 * za1.x + wa2 * za2.x;
            float z0y = wa0 * za0.y + wa1 * za1.y + wa2 * za2.y;
            float z1x = wb0 * zc0.x + wb1 * zc1.x + wb2 * zc2.x;
            float z1y = wb0 * zc0.y + wb1 * zc1.y + wb2 * zc2.y;
            const float b0 = bias[col], b1 = bias[col + 1];
            float v00 = acc[mt][nt][0] + b0 + z0x, v01 = acc[mt][nt][1] + b1 + z0y;
            float v10 = acc[mt][nt][2] + b0 + z1x, v11 = acc[mt][nt][3] + b1 + z1y;
            *(float2*)(out + (size_t)r0 * 256 + col)       = make_float2(v00, v01);
            *(float2*)(out + (size_t)(r0 + 8) * 256 + col) = make_float2(v10, v11);
            sp[nt].x += v00 + v10; sp[nt].y += v01 + v11;
            qp[nt].x += v00 * v00 + v10 * v10; qp[nt].y += v01 * v01 + v11 * v11;
        }
    }
#pragma unroll
    for (int nt = 0; nt < 8; ++nt) {
#pragma unroll
        for (int off = 16; off >= 4; off >>= 1) {
            sp[nt].x += __shfl_xor_sync(0xffffffffu, sp[nt].x, off);
            sp[nt].y += __shfl_xor_sync(0xffffffffu, sp[nt].y, off);
            qp[nt].x += __shfl_xor_sync(0xffffffffu, qp[nt].x, off);
            qp[nt].y += __shfl_xor_sync(0xffffffffu, qp[nt].y, off);
        }
    }
    __syncthreads();
    if (lane < 4) {
#pragma unroll
        for (int nt = 0; nt < 8; ++nt) {
            red_s[(wid * 8 + nt) * 4 + lane] = sp[nt];
            red_q[(wid * 8 + nt) * 4 + lane] = qp[nt];
        }
    }
    __syncthreads();
    if (t < 128) {
        const int wnq = t >> 6, nt = (t >> 3) & 7, lkq = (t >> 1) & 3, hf = t & 1;
        float s = 0.f, q = 0.f;
#pragma unroll
        for (int wq = 0; wq < 4; ++wq) {
            const int w = wq * 2 + wnq;
            float2 a = red_s[(w * 8 + nt) * 4 + lkq];
            float2 c2 = red_q[(w * 8 + nt) * 4 + lkq];
            s += hf ? a.y : a.x;
            q += hf ? c2.y : c2.x;
        }
        psum[(size_t)blockIdx.x * 256 + o0 + t] = s;
        psq [(size_t)blockIdx.x * 256 + o0 + t] = q;
    }
}

// ======== GEMM1: 128x128 tile, K=256; dynamic smem, cp.async B 3-stage ========
#define G1_SMEM ((13312 + 4 * 256) * 4)
__global__ __launch_bounds__(256) void gemm1_kernel(
    const float* __restrict__ A, const float* __restrict__ W,
    const float* __restrict__ bias, float* __restrict__ out,
    const float* __restrict__ scale, const float* __restrict__ shift,
    float* __restrict__ psum, float* __restrict__ psq)
{
    extern __shared__ float dyn[];
    float* As0 = dyn;
    float* Bs0 = dyn + 5120;
    float* ssc = dyn + 12800;
    float* ssh = dyn + 13056;
    float2* red_s = (float2*)(dyn + 13312);
    float2* red_q = red_s + 256;

    const int t = threadIdx.x, wid = t >> 5, lane = t & 31;
    const int j0 = blockIdx.x * 128;
    const int wm = (wid >> 1) * 32, wn = (wid & 1) * 64;
    const int lr = lane >> 2, lk = lane & 3;

    ssc[t] = scale[t]; ssh[t] = shift[t];

    const int arow = t >> 2, akq = (t & 3) * 4;

    float acc[2][8][4];
#pragma unroll
    for (int mt = 0; mt < 2; ++mt)
#pragma unroll
        for (int nt = 0; nt < 8; ++nt)
#pragma unroll
            for (int i = 0; i < 4; ++i) acc[mt][nt][i] = 0.f;

    const float* wg0 = W + (size_t)arow * 256 + akq;
    const float* wg1 = W + (size_t)(arow + 64) * 256 + akq;
    cp16(&Bs0[0 * 2560 + arow * STRD + akq], wg0);
    cp16(&Bs0[0 * 2560 + (arow + 64) * STRD + akq], wg1);
    CP_COMMIT();
    cp16(&Bs0[1 * 2560 + arow * STRD + akq], wg0 + 16);
    cp16(&Bs0[1 * 2560 + (arow + 64) * STRD + akq], wg1 + 16);
    CP_COMMIT();

    float4 pa0, pa1;
    {
        const float* a0 = A + (size_t)(j0 + arow) * 256 + akq;
        pa0 = *(const float4*)a0;
        pa1 = *(const float4*)(a0 + (size_t)64 * 256);
    }
    __syncthreads();

    constexpr int NCHUNK = 16;
    for (int c = 0; c < NCHUNK; ++c) {
        float* Ab = As0 + (c & 1) * 2560;
        float4 va0 = pa0, va1 = pa1;
        {
            const int kb = c * 16 + akq;
            float s0 = ssc[kb], s1 = ssc[kb+1], s2 = ssc[kb+2], s3 = ssc[kb+3];
            float h0 = ssh[kb], h1 = ssh[kb+1], h2 = ssh[kb+2], h3 = ssh[kb+3];
            va0.x = rtf(fmaxf(fmaf(va0.x, s0, h0), 0.f));
            va0.y = rtf(fmaxf(fmaf(va0.y, s1, h1), 0.f));
            va0.z = rtf(fmaxf(fmaf(va0.z, s2, h2), 0.f));
            va0.w = rtf(fmaxf(fmaf(va0.w, s3, h3), 0.f));
            va1.x = rtf(fmaxf(fmaf(va1.x, s0, h0), 0.f));
            va1.y = rtf(fmaxf(fmaf(va1.y, s1, h1), 0.f));
            va1.z = rtf(fmaxf(fmaf(va1.z, s2, h2), 0.f));
            va1.w = rtf(fmaxf(fmaf(va1.w, s3, h3), 0.f));
        }
        *(float4*)&Ab[arow * STRD + akq]        = va0;
        *(float4*)&Ab[(arow + 64) * STRD + akq] = va1;

        if (c + 1 < NCHUNK) {
            const int k0 = (c + 1) * 16;
            const float* a0 = A + (size_t)(j0 + arow) * 256 + k0 + akq;
            pa0 = *(const float4*)a0;
            pa1 = *(const float4*)(a0 + (size_t)64 * 256);
        }
        CP_WAIT1();
        __syncthreads();
        if (c + 2 < NCHUNK) {
            cp16(&Bs0[((c + 2) % 3) * 2560 + arow * STRD + akq], wg0 + (c + 2) * 16);
            cp16(&Bs0[((c + 2) % 3) * 2560 + (arow + 64) * STRD + akq], wg1 + (c + 2) * 16);
        }
        CP_COMMIT();

        const float* Bb = Bs0 + (c % 3) * 2560;
#pragma unroll
        for (int kk = 0; kk < 2; ++kk) {
            uint32_t af[2][4], bf[8][2];
            const int k = kk * 8 + lk;
#pragma unroll
            for (int mt = 0; mt < 2; ++mt) {
                const int r = wm + mt * 16 + lr;
                af[mt][0] = __float_as_uint(Ab[r * STRD + k]);
                af[mt][1] = __float_as_uint(Ab[(r + 8) * STRD + k]);
                af[mt][2] = __float_as_uint(Ab[r * STRD + k + 4]);
                af[mt][3] = __float_as_uint(Ab[(r + 8) * STRD + k + 4]);
            }
#pragma unroll
            for (int nt = 0; nt < 8; ++nt) {
                const int n = wn + nt * 8 + lr;
                bf[nt][0] = __float_as_uint(Bb[n * STRD + k]);
                bf[nt][1] = __float_as_uint(Bb[n * STRD + k + 4]);
            }
#pragma unroll
            for (int mt = 0; mt < 2; ++mt)
#pragma unroll
                for (int nt = 0; nt < 8; ++nt)
                    mma16n8k8(acc[mt][nt], af[mt], bf[nt]);
        }
    }
    CP_WAIT0();

    float2 sp[8], qp[8];
#pragma unroll
    for (int nt = 0; nt < 8; ++nt) { sp[nt] = make_float2(0.f, 0.f); qp[nt] = make_float2(0.f, 0.f); }
#pragma unroll
    for (int mt = 0; mt < 2; ++mt) {
        const int r0 = j0 + wm + mt * 16 + lr;
#pragma unroll
        for (int nt = 0; nt < 8; ++nt) {
            const int col = wn + nt * 8 + 2 * lk;
            const float b0 = bias[col], b1 = bias[col + 1];
            float v00 = acc[mt][nt][0] + b0, v01 = acc[mt][nt][1] + b1;
            float v10 = acc[mt][nt][2] + b0, v11 = acc[mt][nt][3] + b1;
            *(float2*)(out + (size_t)r0 * 128 + col)       = make_float2(v00, v01);
            *(float2*)(out + (size_t)(r0 + 8) * 128 + col) = make_float2(v10, v11);
            sp[nt].x += v00 + v10; sp[nt].y += v01 + v11;
            qp[nt].x += v00 * v00 + v10 * v10; qp[nt].y += v01 * v01 + v11 * v11;
        }
    }
#pragma unroll
    for (int nt = 0; nt < 8; ++nt) {
#pragma unroll
        for (int off = 16; off >= 4; off >>= 1) {
            sp[nt].x += __shfl_xor_sync(0xffffffffu, sp[nt].x, off);
            sp[nt].y += __shfl_xor_sync(0xffffffffu, sp[nt].y, off);
            qp[nt].x += __shfl_xor_sync(0xffffffffu, qp[nt].x, off);
            qp[nt].y += __shfl_xor_sync(0xffffffffu, qp[nt].y, off);
        }
    }
    __syncthreads();
    if (lane < 4) {
#pragma unroll
        for (int nt = 0; nt < 8; ++nt) {
            red_s[(wid * 8 + nt) * 4 + lane] = sp[nt];
            red_q[(wid * 8 + nt) * 4 + lane] = qp[nt];
        }
    }
    __syncthreads();
    if (t < 128) {
        const int wnq = t >> 6, nt = (t >> 3) & 7, lkq = (t >> 1) & 3, hf = t & 1;
        float s = 0.f, q = 0.f;
#pragma unroll
        for (int wq = 0; wq < 4; ++wq) {
            const int w = wq * 2 + wnq;
            float2 a = red_s[(w * 8 + nt) * 4 + lkq];
            float2 c2 = red_q[(w * 8 + nt) * 4 + lkq];
            s += hf ? a.y : a.x;
            q += hf ? c2.y : c2.x;
        }
        psum[(size_t)blockIdx.x * 128 + t] = s;
        psq [(size_t)blockIdx.x * 128 + t] = q;
    }
}

// ---------------- finalize BN scale/shift ----------------
__global__ void finalize_bn(const float* __restrict__ psum, const float* __restrict__ psq,
                            int C, const float* __restrict__ gamma, const float* __restrict__ beta,
                            float* __restrict__ scale, float* __restrict__ shift) {
    const int o = threadIdx.x;
    if (o >= C) return;
    float s = 0.f, q = 0.f;
    for (int r = 0; r < NRB; ++r) { s += psum[(size_t)r * C + o]; q += psq[(size_t)r * C + o]; }
    const float invn = 1.f / (float)JJ;
    float m = s * invn;
    float var = q * invn - m * m;
    float sc = gamma[o] * rsqrtf(var + 1e-5f);
    scale[o] = sc;
    shift[o] = beta[o] - m * sc;
}

// ---------------- output: BN1+ReLU + transpose to (B,128,N) ----------------
__global__ void output_kernel(float* __restrict__ out) {
    __shared__ float tile[32][33];
    const int b = blockIdx.z;
    const int n0 = blockIdx.x * 32, p0 = blockIdx.y * 32;
    const int tx = threadIdx.x;
    for (int i = threadIdx.y; i < 32; i += 8) {
        int p = p0 + tx, n = n0 + i;
        float v = g_y1[((size_t)b * NN + n) * 128 + p];
        tile[i][tx] = fmaxf(fmaf(v, g_sc1[p], g_sh1[p]), 0.f);
    }
    __syncthreads();
    for (int i = threadIdx.y; i < 32; i += 8)
        out[((size_t)(b * 128) + p0 + i) * NN + n0 + tx] = tile[tx][i];
}

// ---------------- launch ----------------
extern "C" void kernel_launch(void* const* d_in, const int* in_sizes, int n_in,
                              void* d_out, int out_size) {
    const float* xyz1    = (const float*)d_in[0];
    const float* xyz2    = (const float*)d_in[1];
    const float* points1 = (const float*)d_in[2];
    const float* points2 = (const float*)d_in[3];
    const float* w0      = (const float*)d_in[4];
    const float* b0      = (const float*)d_in[5];
    const float* gamma0  = (const float*)d_in[6];
    const float* beta0   = (const float*)d_in[7];
    const float* w1      = (const float*)d_in[8];
    const float* b1      = (const float*)d_in[9];
    const float* gamma1  = (const float*)d_in[10];
    const float* beta1   = (const float*)d_in[11];
    float* out = (float*)d_out;

    float *zbuf, *w0t, *w1t, *y0, *y1, *p0s, *p0q, *p1s, *p1q, *sc0, *sh0, *sc1, *sh1;
    cudaGetSymbolAddress((void**)&zbuf, g_z);
    cudaGetSymbolAddress((void**)&w0t,  g_w0t);
    cudaGetSymbolAddress((void**)&w1t,  g_w1t);
    cudaGetSymbolAddress((void**)&y0,   g_y0);
    cudaGetSymbolAddress((void**)&y1,   g_y1);
    cudaGetSymbolAddress((void**)&p0s,  g_p0s);
    cudaGetSymbolAddress((void**)&p0q,  g_p0q);
    cudaGetSymbolAddress((void**)&p1s,  g_p1s);
    cudaGetSymbolAddress((void**)&p1q,  g_p1q);
    cudaGetSymbolAddress((void**)&sc0,  g_sc0);
    cudaGetSymbolAddress((void**)&sh0,  g_sh0);
    cudaGetSymbolAddress((void**)&sc1,  g_sc1);
    cudaGetSymbolAddress((void**)&sh1,  g_sh1);

    cudaFuncSetAttribute(gemm1_kernel, cudaFuncAttributeMaxDynamicSharedMemorySize, G1_SMEM);

    // 1: pre-round weights
    prep_w<<<CCV, 256>>>(w0, w1);
    // 2: knn candidates
    knn_part<<<dim3(NN / 256, BB, KSPLIT), 256>>>(xyz1, xyz2);
    // 3: merge
    knn_merge<<<JJ / 256, 256>>>();
    // 4 (profiled): Z = T(points2) @ W0b^T, 128x64 tile
    //    grid.x = (SS/128 row-blocks per batch) * BB = 16 * 4 = 64
    gemmz_kernel<<<dim3((SS / 128) * BB, 4), 256>>>(points2, w0t + 128, zbuf);
    // 5: y0 = T(points1) @ W0a^T + b0 + gather(Z), + BN partials
    gemm0_kernel<<<dim3(NRB, 2), 256>>>(points1, w0t, b0, y0, p0s, p0q);
    // 6: BN0 finalize
    finalize_bn<<<1, 256>>>(p0s, p0q, 256, gamma0, beta0, sc0, sh0);
    // 7: y1 = relu(bn0(y0)) @ W1^T + b1, + BN partials
    gemm1_kernel<<<NRB, 256, G1_SMEM>>>(y0, w1t, b1, y1, sc0, sh0, p1s, p1q);
    // 8: BN1 finalize
    finalize_bn<<<1, 128>>>(p1s, p1q, 128, gamma1, beta1, sc1, sh1);
    // 9: output transpose + BN1 + ReLU
    output_kernel<<<dim3(NN / 32, 128 / 32, BB), dim3(32, 8)>>>(out);
}

// round 16
// speedup vs baseline: 1.2373x; 1.0437x over previous
#include <cuda_runtime.h>
#include <cstdint>

#define BB 4
#define NN 8192
#define SS 2048
#define C1V 128
#define C2V 256
#define CCV 384
#define JJ (BB*NN)        // 32768
#define JZ (BB*SS)        // 8192
#define NRB (JJ/128)      // 256
#define KSPLIT 4
#define SCHUNK (SS/KSPLIT)  // 512

// ---------------- device scratch ----------------
__device__ float g_z[(size_t)JZ*256];
__device__ float g_w0t[256*CCV];
__device__ float g_w1t[128*256];
__device__ float g_kd[KSPLIT*JJ*3];
__device__ int   g_ki[KSPLIT*JJ*3];
__device__ int   g_idx[JJ*3];
__device__ float g_wgt[JJ*3];
__device__ float g_y0[(size_t)JJ*256];
__device__ float g_y1[(size_t)JJ*128];
__device__ float g_p0s[NRB*256], g_p0q[NRB*256];
__device__ float g_p1s[NRB*128], g_p1q[NRB*128];
__device__ float g_sc0[256], g_sh0[256];
__device__ float g_sc1[128], g_sh1[128];

// ---------------- side stream for graph fork (static init: before any harness checkpoint) ----------------
static cudaStream_t g_s2;
static cudaEvent_t  g_e0, g_e1;
static struct StreamInit {
    StreamInit() {
        cudaStreamCreateWithFlags(&g_s2, cudaStreamNonBlocking);
        cudaEventCreateWithFlags(&g_e0, cudaEventDisableTiming);
        cudaEventCreateWithFlags(&g_e1, cudaEventDisableTiming);
    }
} g_streaminit;

// ---------------- helpers ----------------
__device__ __forceinline__ uint32_t f2tf32(float x) {
    uint32_t r;
    asm("cvt.rna.tf32.f32 %0, %1;" : "=r"(r) : "f"(x));
    return r;
}
__device__ __forceinline__ float rtf(float x) { return __uint_as_float(f2tf32(x)); }
__device__ __forceinline__ void mma16n8k8(float* c, const uint32_t* a, const uint32_t* b) {
    asm volatile(
        "mma.sync.aligned.m16n8k8.row.col.f32.tf32.tf32.f32 "
        "{%0,%1,%2,%3}, {%4,%5,%6,%7}, {%8,%9}, {%0,%1,%2,%3};"
        : "+f"(c[0]), "+f"(c[1]), "+f"(c[2]), "+f"(c[3])
        : "r"(a[0]), "r"(a[1]), "r"(a[2]), "r"(a[3]), "r"(b[0]), "r"(b[1]));
}
__device__ __forceinline__ void cp16(float* smem, const float* gmem) {
    uint32_t sa = (uint32_t)__cvta_generic_to_shared(smem);
    asm volatile("cp.async.ca.shared.global [%0], [%1], 16;" :: "r"(sa), "l"(gmem));
}
#define CP_COMMIT() asm volatile("cp.async.commit_group;" ::: "memory")
#define CP_WAIT1()  asm volatile("cp.async.wait_group 1;" ::: "memory")
#define CP_WAIT0()  asm volatile("cp.async.wait_group 0;" ::: "memory")

// ---------------- K0: pre-round weights to tf32 ----------------
__global__ void prep_w(const float* __restrict__ w0, const float* __restrict__ w1) {
    int i = blockIdx.x * 256 + threadIdx.x;
    if (i < 256 * CCV) g_w0t[i] = rtf(w0[i]);
    if (i < 128 * 256) g_w1t[i] = rtf(w1[i]);
}

// ---------------- K1: 3-NN over one S-chunk ----------------
__global__ void knn_part(const float* __restrict__ xyz1, const float* __restrict__ xyz2) {
    __shared__ float4 pts[SCHUNK];
    const int b = blockIdx.y, half = blockIdx.z, soff = half * SCHUNK;
    const float* x2 = xyz2 + (size_t)b * 3 * SS + soff;
    for (int s = threadIdx.x; s < SCHUNK; s += blockDim.x) {
        float x = x2[s], y = x2[SS + s], z = x2[2 * SS + s];
        pts[s] = make_float4(x, y, z, x * x + y * y + z * z);
    }
    __syncthreads();
    const int n = blockIdx.x * blockDim.x + threadIdx.x;
    const float* x1 = xyz1 + (size_t)b * 3 * NN;
    const float qx = x1[n], qy = x1[NN + n], qz = x1[2 * NN + n];
    const float qn = qx * qx + qy * qy + qz * qz;
    float d0 = 3.4e38f, d1 = 3.4e38f, d2 = 3.4e38f;
    int   i0 = 0, i1 = 0, i2 = 0;
#pragma unroll 4
    for (int s = 0; s < SCHUNK; ++s) {
        float4 p = pts[s];
        float dot = fmaf(qx, p.x, fmaf(qy, p.y, qz * p.z));
        float d = fmaf(-2.f, dot, qn + p.w);
        if (d < d2) {
            if (d < d1) {
                d2 = d1; i2 = i1;
                if (d < d0) { d1 = d0; i1 = i0; d0 = d; i0 = s; }
                else        { d1 = d;  i1 = s; }
            } else { d2 = d; i2 = s; }
        }
    }
    const int j = b * NN + n;
    const size_t o = ((size_t)half * JJ + j) * 3;
    g_kd[o + 0] = d0; g_kd[o + 1] = d1; g_kd[o + 2] = d2;
    g_ki[o + 0] = soff + i0; g_ki[o + 1] = soff + i1; g_ki[o + 2] = soff + i2;
}

// ---------------- K1b: merge candidate lists + weights ----------------
__global__ void knn_merge() {
    const int j = blockIdx.x * 256 + threadIdx.x;
    float md0 = 3.4e38f, md1 = 3.4e38f, md2 = 3.4e38f;
    int   mi0 = 0, mi1 = 0, mi2 = 0;
#pragma unroll
    for (int h = 0; h < KSPLIT; ++h) {
        const size_t o = ((size_t)h * JJ + j) * 3;
#pragma unroll
        for (int m = 0; m < 3; ++m) {
            float d = g_kd[o + m];
            int   i = g_ki[o + m];
            if (d < md2) {
                if (d < md1) {
                    md2 = md1; mi2 = mi1;
                    if (d < md0) { md1 = md0; mi1 = mi0; md0 = d; mi0 = i; }
                    else         { md1 = d;  mi1 = i; }
                } else { md2 = d; mi2 = i; }
            }
        }
    }
    float r0 = 1.f / (md0 + 1e-8f), r1 = 1.f / (md1 + 1e-8f), r2 = 1.f / (md2 + 1e-8f);
    float inv = 1.f / (r0 + r1 + r2);
    g_idx[j * 3 + 0] = mi0; g_idx[j * 3 + 1] = mi1; g_idx[j * 3 + 2] = mi2;
    g_wgt[j * 3 + 0] = r0 * inv; g_wgt[j * 3 + 1] = r1 * inv; g_wgt[j * 3 + 2] = r2 * inv;
}

#define STRD 20

// ======== Z GEMM: Z = T(points2) @ W0b^T, 128x64 tile, K=256 ========
__global__ __launch_bounds__(256) void gemmz_kernel(
    const float* __restrict__ P2, const float* __restrict__ W, float* __restrict__ out)
{
    __shared__ float As[2][16 * 136];
    __shared__ float Bs[3][64 * STRD];

    const int t = threadIdx.x, wid = t >> 5, lane = t & 31;
    const int bz = blockIdx.x >> 4;
    const int s0 = (blockIdx.x & 15) * 128;
    const int o0 = blockIdx.y * 64;
    const int wm = (wid >> 1) * 32, wn = (wid & 1) * 32;
    const int lr = lane >> 2, lk = lane & 3;
    const int cA = t >> 4, gA = t & 15;
    const int brow = t >> 2, bkq = (t & 3) * 4;

    float acc[2][4][4];
#pragma unroll
    for (int mt = 0; mt < 2; ++mt)
#pragma unroll
        for (int nt = 0; nt < 4; ++nt)
#pragma unroll
            for (int i = 0; i < 4; ++i) acc[mt][nt][i] = 0.f;

    const float* wg = W + (size_t)(o0 + brow) * CCV + bkq;
    const float* ab = P2 + ((size_t)bz * C2V + cA) * SS + s0 + gA * 4;

    cp16(&Bs[0][brow * STRD + bkq], wg);        CP_COMMIT();
    cp16(&Bs[1][brow * STRD + bkq], wg + 16);   CP_COMMIT();
    float4 ra0 = *(const float4*)ab;
    float4 ra1 = *(const float4*)(ab + 64);

    constexpr int NC = 16;
    for (int c = 0; c < NC; ++c) {
        uint4 u0, u1;
        u0.x = f2tf32(ra0.x); u0.y = f2tf32(ra0.y); u0.z = f2tf32(ra0.z); u0.w = f2tf32(ra0.w);
        u1.x = f2tf32(ra1.x); u1.y = f2tf32(ra1.y); u1.z = f2tf32(ra1.z); u1.w = f2tf32(ra1.w);
        float* Ab = As[c & 1];
        *(uint4*)&Ab[cA * 136 + gA * 4]      = u0;
        *(uint4*)&Ab[cA * 136 + 64 + gA * 4] = u1;
        if (c + 1 < NC) {
            const float* ap = ab + (size_t)(c + 1) * 16 * SS;
            ra0 = *(const float4*)ap;
            ra1 = *(const float4*)(ap + 64);
        }
        CP_WAIT1();
        __syncthreads();
        if (c + 2 < NC) cp16(&Bs[(c + 2) % 3][brow * STRD + bkq], wg + (c + 2) * 16);
        CP_COMMIT();

        const float* Bb = Bs[c % 3];
#pragma unroll
        for (int kk = 0; kk < 2; ++kk) {
            uint32_t af[2][4], bf[4][2];
            const int k = kk * 8 + lk;
#pragma unroll
            for (int mt = 0; mt < 2; ++mt) {
                const int r = wm + mt * 16 + lr;
                af[mt][0] = __float_as_uint(Ab[k * 136 + r]);
                af[mt][1] = __float_as_uint(Ab[k * 136 + r + 8]);
                af[mt][2] = __float_as_uint(Ab[(k + 4) * 136 + r]);
                af[mt][3] = __float_as_uint(Ab[(k + 4) * 136 + r + 8]);
            }
#pragma unroll
            for (int nt = 0; nt < 4; ++nt) {
                const int n = wn + nt * 8 + lr;
                bf[nt][0] = __float_as_uint(Bb[n * STRD + k]);
                bf[nt][1] = __float_as_uint(Bb[n * STRD + k + 4]);
            }
#pragma unroll
            for (int mt = 0; mt < 2; ++mt)
#pragma unroll
                for (int nt = 0; nt < 4; ++nt)
                    mma16n8k8(acc[mt][nt], af[mt], bf[nt]);
        }
    }
    CP_WAIT0();

#pragma unroll
    for (int mt = 0; mt < 2; ++mt) {
        const int r0 = s0 + wm + mt * 16 + lr;
#pragma unroll
        for (int nt = 0; nt < 4; ++nt) {
            const int col = o0 + wn + nt * 8 + 2 * lk;
            float* orow = out + ((size_t)bz * SS + r0) * 256 + col;
            *(float2*)orow             = make_float2(acc[mt][nt][0], acc[mt][nt][1]);
            *(float2*)(orow + 8 * 256) = make_float2(acc[mt][nt][2], acc[mt][nt][3]);
        }
    }
}

// ======== GEMM0: 128x128 tile, K=128; cp.async B 3-stage; dyn smem ========
// dyn floats: As[0,4352) 2x16x136, Bs[4352,12032) 3x128x20,
//   sidx[12032,12416), swgt[12416,12800), red_s[12800,13312), red_q[13312,13824)
#define G0_SMEM (13824 * 4)
__global__ __launch_bounds__(256) void gemm0_kernel(
    const float* __restrict__ P1, const float* __restrict__ W,
    const float* __restrict__ bias, float* __restrict__ out,
    float* __restrict__ psum, float* __restrict__ psq)
{
    extern __shared__ float dyn0[];
    float*  Asb  = dyn0;
    float*  Bsb  = dyn0 + 4352;
    int*    sidx = (int*)(dyn0 + 12032);
    float*  swgt = dyn0 + 12416;
    float2* red_s = (float2*)(dyn0 + 12800);
    float2* red_q = (float2*)(dyn0 + 13312);

    const int t = threadIdx.x, wid = t >> 5, lane = t & 31;
    const int j0 = blockIdx.x * 128, o0 = blockIdx.y * 128;
    const int b = j0 >> 13, n0 = j0 & (NN - 1);
    const int wm = (wid >> 1) * 32, wn = (wid & 1) * 64;
    const int lr = lane >> 2, lk = lane & 3;

    if (t < 128) {
#pragma unroll
        for (int m = 0; m < 3; ++m) sidx[t * 3 + m] = g_idx[(size_t)(j0 + t) * 3 + m];
    } else {
        int r = t - 128;
#pragma unroll
        for (int m = 0; m < 3; ++m) swgt[r * 3 + m] = g_wgt[(size_t)(j0 + r) * 3 + m];
    }

    const int cA = t >> 4, gA = t & 15;
    const int brow = t >> 2, bkq = (t & 3) * 4;

    float acc[2][8][4];
#pragma unroll
    for (int mt = 0; mt < 2; ++mt)
#pragma unroll
        for (int nt = 0; nt < 8; ++nt)
#pragma unroll
            for (int i = 0; i < 4; ++i) acc[mt][nt][i] = 0.f;

    const float* wg0 = W + (size_t)(o0 + brow) * CCV + bkq;
    const float* wg1 = W + (size_t)(o0 + brow + 64) * CCV + bkq;
    cp16(&Bsb[0 * 2560 + brow * STRD + bkq], wg0);
    cp16(&Bsb[0 * 2560 + (brow + 64) * STRD + bkq], wg1);
    CP_COMMIT();
    cp16(&Bsb[1 * 2560 + brow * STRD + bkq], wg0 + 16);
    cp16(&Bsb[1 * 2560 + (brow + 64) * STRD + bkq], wg1 + 16);
    CP_COMMIT();

    float4 ra0, ra1;
    {
        const float* ap = P1 + ((size_t)b * C1V + cA) * NN + n0 + gA * 4;
        ra0 = *(const float4*)ap;
        ra1 = *(const float4*)(ap + 64);
    }
    __syncthreads();   // sidx/swgt visible

    constexpr int NCHUNK = 8;
    for (int c = 0; c < NCHUNK; ++c) {
        float* Ab = Asb + (c & 1) * 2176;
        uint4 u0, u1;
        u0.x = f2tf32(ra0.x); u0.y = f2tf32(ra0.y); u0.z = f2tf32(ra0.z); u0.w = f2tf32(ra0.w);
        u1.x = f2tf32(ra1.x); u1.y = f2tf32(ra1.y); u1.z = f2tf32(ra1.z); u1.w = f2tf32(ra1.w);
        *(uint4*)&Ab[cA * 136 + gA * 4]      = u0;
        *(uint4*)&Ab[cA * 136 + 64 + gA * 4] = u1;

        if (c + 1 < NCHUNK) {
            const int k0 = (c + 1) * 16;
            const float* ap = P1 + ((size_t)b * C1V + k0 + cA) * NN + n0 + gA * 4;
            ra0 = *(const float4*)ap;
            ra1 = *(const float4*)(ap + 64);
        }
        CP_WAIT1();
        __syncthreads();
        if (c + 2 < NCHUNK) {
            cp16(&Bsb[((c + 2) % 3) * 2560 + brow * STRD + bkq], wg0 + (c + 2) * 16);
            cp16(&Bsb[((c + 2) % 3) * 2560 + (brow + 64) * STRD + bkq], wg1 + (c + 2) * 16);
        }
        CP_COMMIT();

        const float* Bb = Bsb + (c % 3) * 2560;
#pragma unroll
        for (int kk = 0; kk < 2; ++kk) {
            uint32_t af[2][4], bf[8][2];
            const int k = kk * 8 + lk;
#pragma unroll
            for (int mt = 0; mt < 2; ++mt) {
                const int r = wm + mt * 16 + lr;
                af[mt][0] = __float_as_uint(Ab[k * 136 + r]);
                af[mt][1] = __float_as_uint(Ab[k * 136 + r + 8]);
                af[mt][2] = __float_as_uint(Ab[(k + 4) * 136 + r]);
                af[mt][3] = __float_as_uint(Ab[(k + 4) * 136 + r + 8]);
            }
#pragma unroll
            for (int nt = 0; nt < 8; ++nt) {
                const int n = wn + nt * 8 + lr;
                bf[nt][0] = __float_as_uint(Bb[n * STRD + k]);
                bf[nt][1] = __float_as_uint(Bb[n * STRD + k + 4]);
            }
#pragma unroll
            for (int mt = 0; mt < 2; ++mt)
#pragma unroll
                for (int nt = 0; nt < 8; ++nt)
                    mma16n8k8(acc[mt][nt], af[mt], bf[nt]);
        }
    }
    CP_WAIT0();

    // epilogue: register Z-gather + bias + store + BN partials
    float2 sp[8], qp[8];
#pragma unroll
    for (int nt = 0; nt < 8; ++nt) { sp[nt] = make_float2(0.f, 0.f); qp[nt] = make_float2(0.f, 0.f); }
    const float* zb = g_z + (size_t)b * SS * 256;
#pragma unroll
    for (int mt = 0; mt < 2; ++mt) {
        const int rl0 = wm + mt * 16 + lr;
        const int s00 = sidx[rl0 * 3], s01 = sidx[rl0 * 3 + 1], s02 = sidx[rl0 * 3 + 2];
        const float wa0 = swgt[rl0 * 3], wa1 = swgt[rl0 * 3 + 1], wa2 = swgt[rl0 * 3 + 2];
        const int rl1 = rl0 + 8;
        const int s10 = sidx[rl1 * 3], s11 = sidx[rl1 * 3 + 1], s12 = sidx[rl1 * 3 + 2];
        const float wb0 = swgt[rl1 * 3], wb1 = swgt[rl1 * 3 + 1], wb2 = swgt[rl1 * 3 + 2];
        const int r0 = j0 + rl0;
#pragma unroll
        for (int nt = 0; nt < 8; ++nt) {
            const int col = o0 + wn + nt * 8 + 2 * lk;
            float2 za0 = *(const float2*)(zb + (size_t)s00 * 256 + col);
            float2 za1 = *(const float2*)(zb + (size_t)s01 * 256 + col);
            float2 za2 = *(const float2*)(zb + (size_t)s02 * 256 + col);
            float2 zc0 = *(const float2*)(zb + (size_t)s10 * 256 + col);
            float2 zc1 = *(const float2*)(zb + (size_t)s11 * 256 + col);
            float2 zc2 = *(const float2*)(zb + (size_t)s12 * 256 + col);
            float z0x = wa0 * za0.x + wa1 * za1.x + wa2 * za2.x;
            float z0y = wa0 * za0.y + wa1 * za1.y + wa2 * za2.y;
            float z1x = wb0 * zc0.x + wb1 * zc1.x + wb2 * zc2.x;
            float z1y = wb0 * zc0.y + wb1 * zc1.y + wb2 * zc2.y;
            const float b0 = bias[col], b1 = bias[col + 1];
            float v00 = acc[mt][nt][0] + b0 + z0x, v01 = acc[mt][nt][1] + b1 + z0y;
            float v10 = acc[mt][nt][2] + b0 + z1x, v11 = acc[mt][nt][3] + b1 + z1y;
            *(float2*)(out + (size_t)r0 * 256 + col)       = make_float2(v00, v01);
            *(float2*)(out + (size_t)(r0 + 8) * 256 + col) = make_float2(v10, v11);
            sp[nt].x += v00 + v10; sp[nt].y += v01 + v11;
            qp[nt].x += v00 * v00 + v10 * v10; qp[nt].y += v01 * v01 + v11 * v11;
        }
    }
#pragma unroll
    for (int nt = 0; nt < 8; ++nt) {
#pragma unroll
        for (int off = 16; off >= 4; off >>= 1) {
            sp[nt].x += __shfl_xor_sync(0xffffffffu, sp[nt].x, off);
            sp[nt].y += __shfl_xor_sync(0xffffffffu, sp[nt].y, off);
            qp[nt].x += __shfl_xor_sync(0xffffffffu, qp[nt].x, off);
            qp[nt].y += __shfl_xor_sync(0xffffffffu, qp[nt].y, off);
        }
    }
    __syncthreads();
    if (lane < 4) {
#pragma unroll
        for (int nt = 0; nt < 8; ++nt) {
            red_s[(wid * 8 + nt) * 4 + lane] = sp[nt];
            red_q[(wid * 8 + nt) * 4 + lane] = qp[nt];
        }
    }
    __syncthreads();
    if (t < 128) {
        const int wnq = t >> 6, nt = (t >> 3) & 7, lkq = (t >> 1) & 3, hf = t & 1;
        float s = 0.f, q = 0.f;
#pragma unroll
        for (int wq = 0; wq < 4; ++wq) {
            const int w = wq * 2 + wnq;
            float2 a = red_s[(w * 8 + nt) * 4 + lkq];
            float2 c2 = red_q[(w * 8 + nt) * 4 + lkq];
            s += hf ? a.y : a.x;
            q += hf ? c2.y : c2.x;
        }
        psum[(size_t)blockIdx.x * 256 + o0 + t] = s;
        psq [(size_t)blockIdx.x * 256 + o0 + t] = q;
    }
}

// ======== GEMM1: 128x128 tile, K=256; dynamic smem, cp.async B 3-stage ========
#define G1_SMEM ((13312 + 4 * 256) * 4)
__global__ __launch_bounds__(256) void gemm1_kernel(
    const float* __restrict__ A, const float* __restrict__ W,
    const float* __restrict__ bias, float* __restrict__ out,
    const float* __restrict__ scale, const float* __restrict__ shift,
    float* __restrict__ psum, float* __restrict__ psq)
{
    extern __shared__ float dyn[];
    float* As0 = dyn;
    float* Bs0 = dyn + 5120;
    float* ssc = dyn + 12800;
    float* ssh = dyn + 13056;
    float2* red_s = (float2*)(dyn + 13312);
    float2* red_q = red_s + 256;

    const int t = threadIdx.x, wid = t >> 5, lane = t & 31;
    const int j0 = blockIdx.x * 128;
    const int wm = (wid >> 1) * 32, wn = (wid & 1) * 64;
    const int lr = lane >> 2, lk = lane & 3;

    ssc[t] = scale[t]; ssh[t] = shift[t];

    const int arow = t >> 2, akq = (t & 3) * 4;

    float acc[2][8][4];
#pragma unroll
    for (int mt = 0; mt < 2; ++mt)
#pragma unroll
        for (int nt = 0; nt < 8; ++nt)
#pragma unroll
            for (int i = 0; i < 4; ++i) acc[mt][nt][i] = 0.f;

    const float* wg0 = W + (size_t)arow * 256 + akq;
    const float* wg1 = W + (size_t)(arow + 64) * 256 + akq;
    cp16(&Bs0[0 * 2560 + arow * STRD + akq], wg0);
    cp16(&Bs0[0 * 2560 + (arow + 64) * STRD + akq], wg1);
    CP_COMMIT();
    cp16(&Bs0[1 * 2560 + arow * STRD + akq], wg0 + 16);
    cp16(&Bs0[1 * 2560 + (arow + 64) * STRD + akq], wg1 + 16);
    CP_COMMIT();

    float4 pa0, pa1;
    {
        const float* a0 = A + (size_t)(j0 + arow) * 256 + akq;
        pa0 = *(const float4*)a0;
        pa1 = *(const float4*)(a0 + (size_t)64 * 256);
    }
    __syncthreads();

    constexpr int NCHUNK = 16;
    for (int c = 0; c < NCHUNK; ++c) {
        float* Ab = As0 + (c & 1) * 2560;
        float4 va0 = pa0, va1 = pa1;
        {
            const int kb = c * 16 + akq;
            float s0 = ssc[kb], s1 = ssc[kb+1], s2 = ssc[kb+2], s3 = ssc[kb+3];
            float h0 = ssh[kb], h1 = ssh[kb+1], h2 = ssh[kb+2], h3 = ssh[kb+3];
            va0.x = rtf(fmaxf(fmaf(va0.x, s0, h0), 0.f));
            va0.y = rtf(fmaxf(fmaf(va0.y, s1, h1), 0.f));
            va0.z = rtf(fmaxf(fmaf(va0.z, s2, h2), 0.f));
            va0.w = rtf(fmaxf(fmaf(va0.w, s3, h3), 0.f));
            va1.x = rtf(fmaxf(fmaf(va1.x, s0, h0), 0.f));
            va1.y = rtf(fmaxf(fmaf(va1.y, s1, h1), 0.f));
            va1.z = rtf(fmaxf(fmaf(va1.z, s2, h2), 0.f));
            va1.w = rtf(fmaxf(fmaf(va1.w, s3, h3), 0.f));
        }
        *(float4*)&Ab[arow * STRD + akq]        = va0;
        *(float4*)&Ab[(arow + 64) * STRD + akq] = va1;

        if (c + 1 < NCHUNK) {
            const int k0 = (c + 1) * 16;
            const float* a0 = A + (size_t)(j0 + arow) * 256 + k0 + akq;
            pa0 = *(const float4*)a0;
            pa1 = *(const float4*)(a0 + (size_t)64 * 256);
        }
        CP_WAIT1();
        __syncthreads();
        if (c + 2 < NCHUNK) {
            cp16(&Bs0[((c + 2) % 3) * 2560 + arow * STRD + akq], wg0 + (c + 2) * 16);
            cp16(&Bs0[((c + 2) % 3) * 2560 + (arow + 64) * STRD + akq], wg1 + (c + 2) * 16);
        }
        CP_COMMIT();

        const float* Bb = Bs0 + (c % 3) * 2560;
#pragma unroll
        for (int kk = 0; kk < 2; ++kk) {
            uint32_t af[2][4], bf[8][2];
            const int k = kk * 8 + lk;
#pragma unroll
            for (int mt = 0; mt < 2; ++mt) {
                const int r = wm + mt * 16 + lr;
                af[mt][0] = __float_as_uint(Ab[r * STRD + k]);
                af[mt][1] = __float_as_uint(Ab[(r + 8) * STRD + k]);
                af[mt][2] = __float_as_uint(Ab[r * STRD + k + 4]);
                af[mt][3] = __float_as_uint(Ab[(r + 8) * STRD + k + 4]);
            }
#pragma unroll
            for (int nt = 0; nt < 8; ++nt) {
                const int n = wn + nt * 8 + lr;
                bf[nt][0] = __float_as_uint(Bb[n * STRD + k]);
                bf[nt][1] = __float_as_uint(Bb[n * STRD + k + 4]);
            }
#pragma unroll
            for (int mt = 0; mt < 2; ++mt)
#pragma unroll
                for (int nt = 0; nt < 8; ++nt)
                    mma16n8k8(acc[mt][nt], af[mt], bf[nt]);
        }
    }
    CP_WAIT0();

    float2 sp[8], qp[8];
#pragma unroll
    for (int nt = 0; nt < 8; ++nt) { sp[nt] = make_float2(0.f, 0.f); qp[nt] = make_float2(0.f, 0.f); }
#pragma unroll
    for (int mt = 0; mt < 2; ++mt) {
        const int r0 = j0 + wm + mt * 16 + lr;
#pragma unroll
        for (int nt = 0; nt < 8; ++nt) {
            const int col = wn + nt * 8 + 2 * lk;
            const float b0 = bias[col], b1 = bias[col + 1];
            float v00 = acc[mt][nt][0] + b0, v01 = acc[mt][nt][1] + b1;
            float v10 = acc[mt][nt][2] + b0, v11 = acc[mt][nt][3] + b1;
            *(float2*)(out + (size_t)r0 * 128 + col)       = make_float2(v00, v01);
            *(float2*)(out + (size_t)(r0 + 8) * 128 + col) = make_float2(v10, v11);
            sp[nt].x += v00 + v10; sp[nt].y += v01 + v11;
            qp[nt].x += v00 * v00 + v10 * v10; qp[nt].y += v01 * v01 + v11 * v11;
        }
    }
#pragma unroll
    for (int nt = 0; nt < 8; ++nt) {
#pragma unroll
        for (int off = 16; off >= 4; off >>= 1) {
            sp[nt].x += __shfl_xor_sync(0xffffffffu, sp[nt].x, off);
            sp[nt].y += __shfl_xor_sync(0xffffffffu, sp[nt].y, off);
            qp[nt].x += __shfl_xor_sync(0xffffffffu, qp[nt].x, off);
            qp[nt].y += __shfl_xor_sync(0xffffffffu, qp[nt].y, off);
        }
    }
    __syncthreads();
    if (lane < 4) {
#pragma unroll
        for (int nt = 0; nt < 8; ++nt) {
            red_s[(wid * 8 + nt) * 4 + lane] = sp[nt];
            red_q[(wid * 8 + nt) * 4 + lane] = qp[nt];
        }
    }
    __syncthreads();
    if (t < 128) {
        const int wnq = t >> 6, nt = (t >> 3) & 7, lkq = (t >> 1) & 3, hf = t & 1;
        float s = 0.f, q = 0.f;
#pragma unroll
        for (int wq = 0; wq < 4; ++wq) {
            const int w = wq * 2 + wnq;
            float2 a = red_s[(w * 8 + nt) * 4 + lkq];
            float2 c2 = red_q[(w * 8 + nt) * 4 + lkq];
            s += hf ? a.y : a.x;
            q += hf ? c2.y : c2.x;
        }
        psum[(size_t)blockIdx.x * 128 + t] = s;
        psq [(size_t)blockIdx.x * 128 + t] = q;
    }
}

// ---------------- finalize BN scale/shift ----------------
__global__ void finalize_bn(const float* __restrict__ psum, const float* __restrict__ psq,
                            int C, const float* __restrict__ gamma, const float* __restrict__ beta,
                            float* __restrict__ scale, float* __restrict__ shift) {
    const int o = threadIdx.x;
    if (o >= C) return;
    float s = 0.f, q = 0.f;
    for (int r = 0; r < NRB; ++r) { s += psum[(size_t)r * C + o]; q += psq[(size_t)r * C + o]; }
    const float invn = 1.f / (float)JJ;
    float m = s * invn;
    float var = q * invn - m * m;
    float sc = gamma[o] * rsqrtf(var + 1e-5f);
    scale[o] = sc;
    shift[o] = beta[o] - m * sc;
}

// ---------------- output: BN1+ReLU + transpose to (B,128,N) ----------------
__global__ void output_kernel(float* __restrict__ out) {
    __shared__ float tile[32][33];
    const int b = blockIdx.z;
    const int n0 = blockIdx.x * 32, p0 = blockIdx.y * 32;
    const int tx = threadIdx.x;
    for (int i = threadIdx.y; i < 32; i += 8) {
        int p = p0 + tx, n = n0 + i;
        float v = g_y1[((size_t)b * NN + n) * 128 + p];
        tile[i][tx] = fmaxf(fmaf(v, g_sc1[p], g_sh1[p]), 0.f);
    }
    __syncthreads();
    for (int i = threadIdx.y; i < 32; i += 8)
        out[((size_t)(b * 128) + p0 + i) * NN + n0 + tx] = tile[tx][i];
}

// ---------------- launch ----------------
extern "C" void kernel_launch(void* const* d_in, const int* in_sizes, int n_in,
                              void* d_out, int out_size) {
    const float* xyz1    = (const float*)d_in[0];
    const float* xyz2    = (const float*)d_in[1];
    const float* points1 = (const float*)d_in[2];
    const float* points2 = (const float*)d_in[3];
    const float* w0      = (const float*)d_in[4];
    const float* b0      = (const float*)d_in[5];
    const float* gamma0  = (const float*)d_in[6];
    const float* beta0   = (const float*)d_in[7];
    const float* w1      = (const float*)d_in[8];
    const float* b1      = (const float*)d_in[9];
    const float* gamma1  = (const float*)d_in[10];
    const float* beta1   = (const float*)d_in[11];
    float* out = (float*)d_out;

    float *zbuf, *w0t, *w1t, *y0, *y1, *p0s, *p0q, *p1s, *p1q, *sc0, *sh0, *sc1, *sh1;
    cudaGetSymbolAddress((void**)&zbuf, g_z);
    cudaGetSymbolAddress((void**)&w0t,  g_w0t);
    cudaGetSymbolAddress((void**)&w1t,  g_w1t);
    cudaGetSymbolAddress((void**)&y0,   g_y0);
    cudaGetSymbolAddress((void**)&y1,   g_y1);
    cudaGetSymbolAddress((void**)&p0s,  g_p0s);
    cudaGetSymbolAddress((void**)&p0q,  g_p0q);
    cudaGetSymbolAddress((void**)&p1s,  g_p1s);
    cudaGetSymbolAddress((void**)&p1q,  g_p1q);
    cudaGetSymbolAddress((void**)&sc0,  g_sc0);
    cudaGetSymbolAddress((void**)&sh0,  g_sh0);
    cudaGetSymbolAddress((void**)&sc1,  g_sc1);
    cudaGetSymbolAddress((void**)&sh1,  g_sh1);

    cudaFuncSetAttribute(gemm0_kernel, cudaFuncAttributeMaxDynamicSharedMemorySize, G0_SMEM);
    cudaFuncSetAttribute(gemm1_kernel, cudaFuncAttributeMaxDynamicSharedMemorySize, G1_SMEM);

    // Fork: knn chain on side stream, prep_w+gemmz on main stream.
    cudaEventRecord(g_e0, 0);
    cudaStreamWaitEvent(g_s2, g_e0, 0);
    knn_part<<<dim3(NN / 256, BB, KSPLIT), 256, 0, g_s2>>>(xyz1, xyz2);
    knn_merge<<<JJ / 256, 256, 0, g_s2>>>();
    cudaEventRecord(g_e1, g_s2);

    prep_w<<<CCV, 256>>>(w0, w1);
    gemmz_kernel<<<dim3((SS / 128) * BB, 4), 256>>>(points2, w0t + 128, zbuf);

    // Join before gemm0 (needs knn results).
    cudaStreamWaitEvent(0, g_e1, 0);
    gemm0_kernel<<<dim3(NRB, 2), 256, G0_SMEM>>>(points1, w0t, b0, y0, p0s, p0q);
    finalize_bn<<<1, 256>>>(p0s, p0q, 256, gamma0, beta0, sc0, sh0);
    gemm1_kernel<<<NRB, 256, G1_SMEM>>>(y0, w1t, b1, y1, sc0, sh0, p1s, p1q);
    finalize_bn<<<1, 128>>>(p1s, p1q, 128, gamma1, beta1, sc1, sh1);
    output_kernel<<<dim3(NN / 32, 128 / 32, BB), dim3(32, 8)>>>(out);
}